// round 12
// baseline (speedup 1.0000x reference)
#include <cuda_runtime.h>
#include <cuda_bf16.h>
#include <cuda_fp16.h>
#include <math.h>
#include <stdint.h>

#define Tn 2048
#define Dn 1024
#define En 8
#define Fn 2048
#define Vn 32000
#define CAPn 640

// ---------------- device scratch ----------------
__device__ float g_hA[Tn * Dn];
__device__ float g_hB[Tn * Dn];
__device__ int   g_top2[Tn * 2];
__device__ float g_topw[Tn * 2];
__device__ float g_wkept[Tn * 2];
__device__ int   g_elist[En * CAPn];
__device__ float g_ew[En * CAPn];
__device__ int   g_ecnt[En];
__device__ __nv_bfloat16 g_Ah[Tn * Dn];
__device__ __nv_bfloat16 g_Al[Tn * Dn];
__device__ __half g_Ap[Tn * Dn];
__device__ __nv_bfloat16 g_w1h[(size_t)En * Fn * Dn];
__device__ __nv_bfloat16 g_w1l[(size_t)En * Fn * Dn];
__device__ __half        g_w1p[(size_t)En * Fn * Dn];
__device__ __nv_bfloat16 g_w2h[(size_t)En * Dn * Fn];
__device__ __nv_bfloat16 g_w2l[(size_t)En * Dn * Fn];
__device__ __half        g_w2p[(size_t)En * Dn * Fn];
__device__ __nv_bfloat16 g_hidh[(size_t)En * CAPn * Fn];
__device__ __nv_bfloat16 g_hidl[(size_t)En * CAPn * Fn];
__device__ __half        g_hidp[(size_t)En * CAPn * Fn];

__device__ __forceinline__ float gelu_t(float x) {
    float u = 0.7978845608028654f * (x + 0.044715f * x * x * x);
    return 0.5f * x * (1.0f + tanhf(u));
}

// ---------------- hmma helpers ----------------
__device__ __forceinline__ uint32_t s2u(const void* p) {
    uint32_t a;
    asm("{ .reg .u64 t; cvta.to.shared.u64 t, %1; cvt.u32.u64 %0, t; }" : "=r"(a) : "l"(p));
    return a;
}
__device__ __forceinline__ void ldsm4(uint32_t* r, uint32_t a) {
    asm volatile("ldmatrix.sync.aligned.m8n8.x4.shared.b16 {%0,%1,%2,%3}, [%4];"
                 : "=r"(r[0]), "=r"(r[1]), "=r"(r[2]), "=r"(r[3]) : "r"(a));
}
__device__ __forceinline__ void mma16816(float* c, const uint32_t* a, uint32_t b0, uint32_t b1) {
    asm volatile("mma.sync.aligned.m16n8k16.row.col.f32.bf16.bf16.f32 "
                 "{%0,%1,%2,%3}, {%4,%5,%6,%7}, {%8,%9}, {%0,%1,%2,%3};"
                 : "+f"(c[0]), "+f"(c[1]), "+f"(c[2]), "+f"(c[3])
                 : "r"(a[0]), "r"(a[1]), "r"(a[2]), "r"(a[3]), "r"(b0), "r"(b1));
}
__device__ __forceinline__ void mma16816h(float* c, const uint32_t* a, uint32_t b0, uint32_t b1) {
    asm volatile("mma.sync.aligned.m16n8k16.row.col.f32.f16.f16.f32 "
                 "{%0,%1,%2,%3}, {%4,%5,%6,%7}, {%8,%9}, {%0,%1,%2,%3};"
                 : "+f"(c[0]), "+f"(c[1]), "+f"(c[2]), "+f"(c[3])
                 : "r"(a[0]), "r"(a[1]), "r"(a[2]), "r"(a[3]), "r"(b0), "r"(b1));
}
__device__ __forceinline__ void cpa16(uint32_t dst, const void* src) {
    asm volatile("cp.async.cg.shared.global [%0], [%1], 16;" :: "r"(dst), "l"(src) : "memory");
}
__device__ __forceinline__ void bsplit(float x, unsigned short& h, unsigned short& l) {
    __nv_bfloat16 hb = __float2bfloat16_rn(x);
    __nv_bfloat16 lb = __float2bfloat16_rn(x - __bfloat162float(hb));
    h = *(unsigned short*)&hb;
    l = *(unsigned short*)&lb;
}

// ---------------- embedding gather ----------------
__global__ void k_embed(const int* __restrict__ ids, const float* __restrict__ ew) {
    int i = blockIdx.x * blockDim.x + threadIdx.x;
    int t = i / (Dn / 4);
    int d4 = i % (Dn / 4);
    float4 v = ((const float4*)(ew + (size_t)ids[t] * Dn))[d4];
    ((float4*)(g_hA + (size_t)t * Dn))[d4] = v;
}

// ---------------- fused per-hop h prep ----------------
__global__ void k_prep_h(const float* __restrict__ hin, float* __restrict__ hout,
                         __nv_bfloat16* __restrict__ hi, __nv_bfloat16* __restrict__ lo,
                         __half* __restrict__ fp, int mode) {
    int t = blockIdx.x;
    int i = (size_t)t * (Dn / 4) + threadIdx.x;
    float4 v = ((const float4*)hin)[i];
    if (mode == 0) {
        float x[4] = {v.x, v.y, v.z, v.w};
        unsigned short h[4], l[4];
        #pragma unroll
        for (int j = 0; j < 4; j++) bsplit(x[j], h[j], l[j]);
        ((uint2*)hi)[i] = make_uint2((uint32_t)h[0] | ((uint32_t)h[1] << 16),
                                     (uint32_t)h[2] | ((uint32_t)h[3] << 16));
        ((uint2*)lo)[i] = make_uint2((uint32_t)l[0] | ((uint32_t)l[1] << 16),
                                     (uint32_t)l[2] | ((uint32_t)l[3] << 16));
    } else {
        __half2 a = __floats2half2_rn(v.x, v.y);
        __half2 b = __floats2half2_rn(v.z, v.w);
        ((uint2*)fp)[i] = make_uint2(*(uint32_t*)&a, *(uint32_t*)&b);
    }
    float s = 1.0f - (g_wkept[2 * t] + g_wkept[2 * t + 1]);
    v.x *= s; v.y *= s; v.z *= s; v.w *= s;
    ((float4*)hout)[i] = v;
}

// ---------------- fused transpose+split: fp32 [E][R][C] -> bf16 hi/lo + fp16 [E][C][R] ----------------
__global__ void k_tspl3(const float* __restrict__ src, __nv_bfloat16* __restrict__ hi,
                        __nv_bfloat16* __restrict__ lo, __half* __restrict__ fp,
                        int R, int C) {
    __shared__ float t[64][33];
    int e = blockIdx.z;
    const float* S = src + (size_t)e * R * C;
    __nv_bfloat16* H = hi + (size_t)e * R * C;
    __nv_bfloat16* L = lo + (size_t)e * R * C;
    __half* P = fp + (size_t)e * R * C;
    int c0 = blockIdx.x * 32, r0 = blockIdx.y * 64;
    int tx = threadIdx.x & 31, ty = threadIdx.x >> 5;
    #pragma unroll
    for (int j = 0; j < 8; j++)
        t[ty + j * 8][tx] = S[(size_t)(r0 + ty + j * 8) * C + c0 + tx];
    __syncthreads();
    int c = threadIdx.x >> 3, ri = threadIdx.x & 7;
    unsigned short hb[8], lb[8];
    uint32_t pk[4];
    #pragma unroll
    for (int i = 0; i < 8; i++) bsplit(t[ri * 8 + i][c], hb[i], lb[i]);
    #pragma unroll
    for (int i = 0; i < 4; i++) {
        __half2 p = __floats2half2_rn(t[ri * 8 + 2 * i][c], t[ri * 8 + 2 * i + 1][c]);
        pk[i] = *(uint32_t*)&p;
    }
    size_t o = (size_t)(c0 + c) * R + r0 + ri * 8;
    *(uint4*)&H[o] = make_uint4((uint32_t)hb[0] | ((uint32_t)hb[1] << 16),
                                (uint32_t)hb[2] | ((uint32_t)hb[3] << 16),
                                (uint32_t)hb[4] | ((uint32_t)hb[5] << 16),
                                (uint32_t)hb[6] | ((uint32_t)hb[7] << 16));
    *(uint4*)&L[o] = make_uint4((uint32_t)lb[0] | ((uint32_t)lb[1] << 16),
                                (uint32_t)lb[2] | ((uint32_t)lb[3] << 16),
                                (uint32_t)lb[4] | ((uint32_t)lb[5] << 16),
                                (uint32_t)lb[6] | ((uint32_t)lb[7] << 16));
    *(uint4*)&P[o] = make_uint4(pk[0], pk[1], pk[2], pk[3]);
}

// ---------------- router ----------------
__global__ void k_router(const float* __restrict__ h, const float* __restrict__ rw) {
    int t = blockIdx.x;
    int lane = threadIdx.x & 31;
    int w = threadIdx.x >> 5;
    const float* hr = h + (size_t)t * Dn;
    float acc = 0.f;
    for (int d = lane; d < Dn; d += 32) acc += hr[d] * rw[d * En + w];
    #pragma unroll
    for (int o = 16; o; o >>= 1) acc += __shfl_xor_sync(0xFFFFFFFFu, acc, o);
    __shared__ float lg[En];
    if (lane == 0) lg[w] = acc;
    __syncthreads();
    if (threadIdx.x == 0) {
        float l[En];
        #pragma unroll
        for (int e = 0; e < En; e++) l[e] = lg[e];
        float m = l[0];
        #pragma unroll
        for (int e = 1; e < En; e++) m = fmaxf(m, l[e]);
        float p[En], s = 0.f;
        #pragma unroll
        for (int e = 0; e < En; e++) { p[e] = expf(l[e] - m); s += p[e]; }
        float inv = 1.0f / s;
        int i0 = 0;
        #pragma unroll
        for (int e = 1; e < En; e++) if (l[e] > l[i0]) i0 = e;
        int i1 = -1;
        #pragma unroll
        for (int e = 0; e < En; e++) {
            if (e == i0) continue;
            if (i1 < 0 || l[e] > l[i1]) i1 = e;
        }
        g_top2[2 * t] = i0;
        g_top2[2 * t + 1] = i1;
        g_topw[2 * t] = p[i0] * inv;
        g_topw[2 * t + 1] = p[i1] * inv;
        g_wkept[2 * t] = 0.f;
        g_wkept[2 * t + 1] = 0.f;
    }
}

// ---------------- capacity scan ----------------
__global__ void k_scan() {
    __shared__ int s_top[Tn * 2];
    for (int i = threadIdx.x; i < Tn * 2; i += 256) s_top[i] = g_top2[i];
    __syncthreads();
    int lane = threadIdx.x & 31;
    int e = threadIdx.x >> 5;
    if (e >= En) return;
    int base = 0;
    for (int t0 = 0; t0 < Tn; t0 += 32) {
        int t = t0 + lane;
        int a = s_top[2 * t], b = s_top[2 * t + 1];
        int j = (a == e) ? 0 : ((b == e) ? 1 : -1);
        unsigned bal = __ballot_sync(0xFFFFFFFFu, j >= 0);
        int rank = base + __popc(bal & (0xFFFFFFFFu >> (31 - lane)));
        if (j >= 0 && rank <= CAPn) {
            int slot = rank - 1;
            g_elist[e * CAPn + slot] = t;
            float wv = g_topw[2 * t + j];
            g_ew[e * CAPn + slot] = wv;
            g_wkept[2 * t + j] = wv;
        }
        base += __popc(bal);
    }
    if (lane == 0) g_ecnt[e] = base < CAPn ? base : CAPn;
}

// ---------------- fused final rmsnorm -> fp16 ----------------
__global__ void k_rms_fp16(const float* __restrict__ hin, const float* __restrict__ lnw,
                           __half* __restrict__ Ap) {
    int t = blockIdx.x;
    int lane = threadIdx.x & 31, wid = threadIdx.x >> 5;
    float4 v = ((const float4*)(hin + (size_t)t * Dn))[threadIdx.x];
    float s = v.x * v.x + v.y * v.y + v.z * v.z + v.w * v.w;
    #pragma unroll
    for (int o = 16; o; o >>= 1) s += __shfl_xor_sync(0xFFFFFFFFu, s, o);
    __shared__ float red[8];
    if (lane == 0) red[wid] = s;
    __syncthreads();
    float tot = 0.f;
    #pragma unroll
    for (int i = 0; i < 8; i++) tot += red[i];
    float sc = rsqrtf(tot * (1.0f / Dn) + 1e-6f);
    float4 w = ((const float4*)lnw)[threadIdx.x];
    __half2 a = __floats2half2_rn(v.x * sc * w.x, v.y * sc * w.y);
    __half2 b = __floats2half2_rn(v.z * sc * w.z, v.w * sc * w.w);
    ((uint2*)(Ap + (size_t)t * Dn))[threadIdx.x] = make_uint2(*(uint32_t*)&a, *(uint32_t*)&b);
}

// ================= HMMA tile framework (128x128, proven config) =================
#define ROWB 80
#define ARRB (128 * ROWB)
#define STAGEB (4 * ARRB)
#define STAGE2B (2 * ARRB)
// --- projection with in-kernel fp32->fp16 B convert ---
#define PB32ROW 144                 // 128B data + 16 pad, 16-aligned
#define PB32SZ (128 * PB32ROW)      // 18432
#define P_B32 ARRB                  // staging after A (10240)
#define P_BF (ARRB + PB32SZ)        // 28672
#define PSTG (2 * ARRB + PB32SZ)    // 38912 per stage

#define HMMA_PROLOG \
    extern __shared__ char smraw[]; \
    const uint32_t sbase = s2u(smraw); \
    const int tid = threadIdx.x; \
    const int lane = tid & 31; \
    const int wm = (tid >> 5) & 3; \
    const int wn = tid >> 7; \
    float acc[2][8][4]; \
    _Pragma("unroll") for (int i = 0; i < 2; i++) \
        _Pragma("unroll") for (int j = 0; j < 8; j++) \
            _Pragma("unroll") for (int q = 0; q < 4; q++) acc[i][j][q] = 0.f; \
    const int a_lr = lane & 15; \
    const int a_lc = ((lane >> 4) << 3); \
    const int b_nr = ((lane >> 4) << 3) + (lane & 7); \
    const int b_kc = (lane & 8);

#define HMMA_MAINLOOP(NCHKv) \
    load_stage(0, 0); \
    load_stage(1, 1); \
    for (int c = 0; c < (NCHKv); c++) { \
        const int st = c & 1; \
        if (c + 1 < (NCHKv)) asm volatile("cp.async.wait_group 1;" ::: "memory"); \
        else                 asm volatile("cp.async.wait_group 0;" ::: "memory"); \
        __syncthreads(); \
        const uint32_t sb = sbase + st * STAGEB; \
        _Pragma("unroll") \
        for (int k16 = 0; k16 < 32; k16 += 16) { \
            uint32_t ah[2][4], al[2][4]; \
            _Pragma("unroll") \
            for (int mi = 0; mi < 2; mi++) { \
                uint32_t aoff = (uint32_t)((wm * 32 + mi * 16 + a_lr) * ROWB + (k16 + a_lc) * 2); \
                ldsm4(ah[mi], sb + aoff); \
                ldsm4(al[mi], sb + ARRB + aoff); \
            } \
            _Pragma("unroll") \
            for (int ng = 0; ng < 4; ng++) { \
                uint32_t boff = (uint32_t)((wn * 64 + ng * 16 + b_nr) * ROWB + (k16 + b_kc) * 2); \
                uint32_t bh[4], bl[4]; \
                ldsm4(bh, sb + 2 * ARRB + boff); \
                ldsm4(bl, sb + 3 * ARRB + boff); \
                _Pragma("unroll") \
                for (int hv = 0; hv < 2; hv++) { \
                    const int nj = ng * 2 + hv; \
                    _Pragma("unroll") \
                    for (int mi = 0; mi < 2; mi++) { \
                        mma16816(acc[mi][nj], ah[mi], bh[2 * hv], bh[2 * hv + 1]); \
                        mma16816(acc[mi][nj], al[mi], bh[2 * hv], bh[2 * hv + 1]); \
                        mma16816(acc[mi][nj], ah[mi], bl[2 * hv], bl[2 * hv + 1]); \
                    } \
                } \
            } \
        } \
        __syncthreads(); \
        if (c + 2 < (NCHKv)) load_stage(c + 2, st); \
    }

#define HMMA16_MAINLOOP(NCHKv) \
    load_stage(0, 0); \
    load_stage(1, 1); \
    for (int c = 0; c < (NCHKv); c++) { \
        const int st = c & 1; \
        if (c + 1 < (NCHKv)) asm volatile("cp.async.wait_group 1;" ::: "memory"); \
        else                 asm volatile("cp.async.wait_group 0;" ::: "memory"); \
        __syncthreads(); \
        const uint32_t sb = sbase + st * STAGE2B; \
        _Pragma("unroll") \
        for (int k16 = 0; k16 < 32; k16 += 16) { \
            uint32_t af[2][4]; \
            _Pragma("unroll") \
            for (int mi = 0; mi < 2; mi++) { \
                uint32_t aoff = (uint32_t)((wm * 32 + mi * 16 + a_lr) * ROWB + (k16 + a_lc) * 2); \
                ldsm4(af[mi], sb + aoff); \
            } \
            _Pragma("unroll") \
            for (int ng = 0; ng < 4; ng++) { \
                uint32_t boff = (uint32_t)((wn * 64 + ng * 16 + b_nr) * ROWB + (k16 + b_kc) * 2); \
                uint32_t bf[4]; \
                ldsm4(bf, sb + ARRB + boff); \
                _Pragma("unroll") \
                for (int hv = 0; hv < 2; hv++) { \
                    const int nj = ng * 2 + hv; \
                    _Pragma("unroll") \
                    for (int mi = 0; mi < 2; mi++) \
                        mma16816h(acc[mi][nj], af[mi], bf[2 * hv], bf[2 * hv + 1]); \
                } \
            } \
        } \
        __syncthreads(); \
        if (c + 2 < (NCHKv)) load_stage(c + 2, st); \
    }

// ---------------- hop-1 GEMM1 (bf16 3-term) ----------------
__global__ __launch_bounds__(256, 2)
void k_gemm1_hmma(const __nv_bfloat16* __restrict__ Ah, const __nv_bfloat16* __restrict__ Al) {
    const int e = blockIdx.z;
    const int cnt = g_ecnt[e];
    const int m0 = blockIdx.y * 128;
    if (m0 >= cnt) return;
    HMMA_PROLOG
    const int n0 = blockIdx.x * 128;
    const __nv_bfloat16* Wh = g_w1h + (size_t)e * Fn * Dn;
    const __nv_bfloat16* Wl = g_w1l + (size_t)e * Fn * Dn;
    size_t gaA[2], gaB[2];
    uint32_t soff[2];
    #pragma unroll
    for (int hf = 0; hf < 2; hf++) {
        int id = tid + hf * 256;
        int row = id >> 2, seg = id & 3;
        int mrow = m0 + row;
        if (mrow >= cnt) mrow = cnt - 1;
        int tok = g_elist[e * CAPn + mrow];
        gaA[hf] = (size_t)tok * Dn + seg * 8;
        gaB[hf] = (size_t)(n0 + row) * Dn + seg * 8;
        soff[hf] = (uint32_t)(row * ROWB + seg * 16);
    }
    auto load_stage = [&](int c, int st) {
        const int kb = c * 32;
        const uint32_t sb = sbase + st * STAGEB;
        #pragma unroll
        for (int hf = 0; hf < 2; hf++) {
            cpa16(sb + soff[hf], Ah + gaA[hf] + kb);
            cpa16(sb + ARRB + soff[hf], Al + gaA[hf] + kb);
            cpa16(sb + 2 * ARRB + soff[hf], Wh + gaB[hf] + kb);
            cpa16(sb + 3 * ARRB + soff[hf], Wl + gaB[hf] + kb);
        }
        asm volatile("cp.async.commit_group;" ::: "memory");
    };
    HMMA_MAINLOOP(Dn / 32)
    __nv_bfloat16* Hh = g_hidh + (size_t)e * CAPn * Fn;
    __nv_bfloat16* Hl = g_hidl + (size_t)e * CAPn * Fn;
    const int g = lane >> 2, t2 = (lane & 3) << 1;
    #pragma unroll
    for (int mi = 0; mi < 2; mi++) {
        int r = wm * 32 + mi * 16 + g;
        #pragma unroll
        for (int nj = 0; nj < 8; nj++) {
            int col = n0 + wn * 64 + nj * 8 + t2;
            int s0 = m0 + r, s1 = m0 + r + 8;
            if (s0 < cnt) {
                float x0 = gelu_t(acc[mi][nj][0]), x1 = gelu_t(acc[mi][nj][1]);
                unsigned short h0, l0, h1, l1;
                bsplit(x0, h0, l0);
                bsplit(x1, h1, l1);
                *(uint32_t*)&Hh[(size_t)s0 * Fn + col] = (uint32_t)h0 | ((uint32_t)h1 << 16);
                *(uint32_t*)&Hl[(size_t)s0 * Fn + col] = (uint32_t)l0 | ((uint32_t)l1 << 16);
            }
            if (s1 < cnt) {
                float x2 = gelu_t(acc[mi][nj][2]), x3 = gelu_t(acc[mi][nj][3]);
                unsigned short h2, l2, h3, l3;
                bsplit(x2, h2, l2);
                bsplit(x3, h3, l3);
                *(uint32_t*)&Hh[(size_t)s1 * Fn + col] = (uint32_t)h2 | ((uint32_t)h3 << 16);
                *(uint32_t*)&Hl[(size_t)s1 * Fn + col] = (uint32_t)l2 | ((uint32_t)l3 << 16);
            }
        }
    }
}

// ---------------- hop-1 GEMM2 (bf16 3-term): scatter ----------------
__global__ __launch_bounds__(256, 2)
void k_gemm2_hmma(float* __restrict__ hout) {
    const int e = blockIdx.z;
    const int cnt = g_ecnt[e];
    const int m0 = blockIdx.y * 128;
    if (m0 >= cnt) return;
    HMMA_PROLOG
    const int n0 = blockIdx.x * 128;
    const __nv_bfloat16* Ahp = g_hidh + (size_t)e * CAPn * Fn;
    const __nv_bfloat16* Alp = g_hidl + (size_t)e * CAPn * Fn;
    const __nv_bfloat16* Wh = g_w2h + (size_t)e * Dn * Fn;
    const __nv_bfloat16* Wl = g_w2l + (size_t)e * Dn * Fn;
    size_t gaA[2], gaB[2];
    uint32_t soff[2];
    #pragma unroll
    for (int hf = 0; hf < 2; hf++) {
        int id = tid + hf * 256;
        int row = id >> 2, seg = id & 3;
        gaA[hf] = (size_t)(m0 + row) * Fn + seg * 8;
        gaB[hf] = (size_t)(n0 + row) * Fn + seg * 8;
        soff[hf] = (uint32_t)(row * ROWB + seg * 16);
    }
    auto load_stage = [&](int c, int st) {
        const int kb = c * 32;
        const uint32_t sb = sbase + st * STAGEB;
        #pragma unroll
        for (int hf = 0; hf < 2; hf++) {
            cpa16(sb + soff[hf], Ahp + gaA[hf] + kb);
            cpa16(sb + ARRB + soff[hf], Alp + gaA[hf] + kb);
            cpa16(sb + 2 * ARRB + soff[hf], Wh + gaB[hf] + kb);
            cpa16(sb + 3 * ARRB + soff[hf], Wl + gaB[hf] + kb);
        }
        asm volatile("cp.async.commit_group;" ::: "memory");
    };
    HMMA_MAINLOOP(Fn / 32)
    const int g = lane >> 2, t2 = (lane & 3) << 1;
    #pragma unroll
    for (int mi = 0; mi < 2; mi++) {
        int r = wm * 32 + mi * 16 + g;
        int s0 = m0 + r, s1 = m0 + r + 8;
        int tok0 = 0, tok1 = 0;
        float w0 = 0.f, w1v = 0.f;
        if (s0 < cnt) { tok0 = g_elist[e * CAPn + s0]; w0 = g_ew[e * CAPn + s0]; }
        if (s1 < cnt) { tok1 = g_elist[e * CAPn + s1]; w1v = g_ew[e * CAPn + s1]; }
        #pragma unroll
        for (int nj = 0; nj < 8; nj++) {
            int col = n0 + wn * 64 + nj * 8 + t2;
            if (s0 < cnt) {
                atomicAdd(&hout[(size_t)tok0 * Dn + col], w0 * acc[mi][nj][0]);
                atomicAdd(&hout[(size_t)tok0 * Dn + col + 1], w0 * acc[mi][nj][1]);
            }
            if (s1 < cnt) {
                atomicAdd(&hout[(size_t)tok1 * Dn + col], w1v * acc[mi][nj][2]);
                atomicAdd(&hout[(size_t)tok1 * Dn + col + 1], w1v * acc[mi][nj][3]);
            }
        }
    }
}

// ---------------- hop-2 GEMM1 (fp16 single) ----------------
__global__ __launch_bounds__(256, 2)
void k_gemm1_fp16(const __half* __restrict__ Ap) {
    const int e = blockIdx.z;
    const int cnt = g_ecnt[e];
    const int m0 = blockIdx.y * 128;
    if (m0 >= cnt) return;
    HMMA_PROLOG
    const int n0 = blockIdx.x * 128;
    const __half* Wp = g_w1p + (size_t)e * Fn * Dn;
    size_t gaA[2], gaB[2];
    uint32_t soff[2];
    #pragma unroll
    for (int hf = 0; hf < 2; hf++) {
        int id = tid + hf * 256;
        int row = id >> 2, seg = id & 3;
        int mrow = m0 + row;
        if (mrow >= cnt) mrow = cnt - 1;
        int tok = g_elist[e * CAPn + mrow];
        gaA[hf] = (size_t)tok * Dn + seg * 8;
        gaB[hf] = (size_t)(n0 + row) * Dn + seg * 8;
        soff[hf] = (uint32_t)(row * ROWB + seg * 16);
    }
    auto load_stage = [&](int c, int st) {
        const int kb = c * 32;
        const uint32_t sb = sbase + st * STAGE2B;
        #pragma unroll
        for (int hf = 0; hf < 2; hf++) {
            cpa16(sb + soff[hf], Ap + gaA[hf] + kb);
            cpa16(sb + ARRB + soff[hf], Wp + gaB[hf] + kb);
        }
        asm volatile("cp.async.commit_group;" ::: "memory");
    };
    HMMA16_MAINLOOP(Dn / 32)
    __half* Hp = g_hidp + (size_t)e * CAPn * Fn;
    const int g = lane >> 2, t2 = (lane & 3) << 1;
    #pragma unroll
    for (int mi = 0; mi < 2; mi++) {
        int r = wm * 32 + mi * 16 + g;
        #pragma unroll
        for (int nj = 0; nj < 8; nj++) {
            int col = n0 + wn * 64 + nj * 8 + t2;
            int s0 = m0 + r, s1 = m0 + r + 8;
            if (s0 < cnt) {
                __half2 p = __floats2half2_rn(gelu_t(acc[mi][nj][0]), gelu_t(acc[mi][nj][1]));
                *(uint32_t*)&Hp[(size_t)s0 * Fn + col] = *(uint32_t*)&p;
            }
            if (s1 < cnt) {
                __half2 p = __floats2half2_rn(gelu_t(acc[mi][nj][2]), gelu_t(acc[mi][nj][3]));
                *(uint32_t*)&Hp[(size_t)s1 * Fn + col] = *(uint32_t*)&p;
            }
        }
    }
}

// ---------------- hop-2 GEMM2 (fp16 single): scatter ----------------
__global__ __launch_bounds__(256, 2)
void k_gemm2_fp16(float* __restrict__ hout) {
    const int e = blockIdx.z;
    const int cnt = g_ecnt[e];
    const int m0 = blockIdx.y * 128;
    if (m0 >= cnt) return;
    HMMA_PROLOG
    const int n0 = blockIdx.x * 128;
    const __half* Apx = g_hidp + (size_t)e * CAPn * Fn;
    const __half* Wp = g_w2p + (size_t)e * Dn * Fn;
    size_t gaA[2], gaB[2];
    uint32_t soff[2];
    #pragma unroll
    for (int hf = 0; hf < 2; hf++) {
        int id = tid + hf * 256;
        int row = id >> 2, seg = id & 3;
        gaA[hf] = (size_t)(m0 + row) * Fn + seg * 8;
        gaB[hf] = (size_t)(n0 + row) * Fn + seg * 8;
        soff[hf] = (uint32_t)(row * ROWB + seg * 16);
    }
    auto load_stage = [&](int c, int st) {
        const int kb = c * 32;
        const uint32_t sb = sbase + st * STAGE2B;
        #pragma unroll
        for (int hf = 0; hf < 2; hf++) {
            cpa16(sb + soff[hf], Apx + gaA[hf] + kb);
            cpa16(sb + ARRB + soff[hf], Wp + gaB[hf] + kb);
        }
        asm volatile("cp.async.commit_group;" ::: "memory");
    };
    HMMA16_MAINLOOP(Fn / 32)
    const int g = lane >> 2, t2 = (lane & 3) << 1;
    #pragma unroll
    for (int mi = 0; mi < 2; mi++) {
        int r = wm * 32 + mi * 16 + g;
        int s0 = m0 + r, s1 = m0 + r + 8;
        int tok0 = 0, tok1 = 0;
        float w0 = 0.f, w1v = 0.f;
        if (s0 < cnt) { tok0 = g_elist[e * CAPn + s0]; w0 = g_ew[e * CAPn + s0]; }
        if (s1 < cnt) { tok1 = g_elist[e * CAPn + s1]; w1v = g_ew[e * CAPn + s1]; }
        #pragma unroll
        for (int nj = 0; nj < 8; nj++) {
            int col = n0 + wn * 64 + nj * 8 + t2;
            if (s0 < cnt) {
                atomicAdd(&hout[(size_t)tok0 * Dn + col], w0 * acc[mi][nj][0]);
                atomicAdd(&hout[(size_t)tok0 * Dn + col + 1], w0 * acc[mi][nj][1]);
            }
            if (s1 < cnt) {
                atomicAdd(&hout[(size_t)tok1 * Dn + col], w1v * acc[mi][nj][2]);
                atomicAdd(&hout[(size_t)tok1 * Dn + col + 1], w1v * acc[mi][nj][3]);
            }
        }
    }
}

// ---------------- tied projection: A fp16, B = fp32 embed converted in-kernel ----------------
__global__ __launch_bounds__(256, 2)
void k_proj_fp16(const __half* __restrict__ Ap, const float* __restrict__ B32,
                 float* __restrict__ C) {
    HMMA_PROLOG
    const int m0 = blockIdx.x * 128;
    const int n0 = blockIdx.y * 128;
    // A: fp16, 512 x 16B segs over 2 iterations
    size_t gaA[2];
    uint32_t soffA[2];
    #pragma unroll
    for (int hf = 0; hf < 2; hf++) {
        int id = tid + hf * 256;
        int row = id >> 2, seg = id & 3;
        gaA[hf] = (size_t)(m0 + row) * Dn + seg * 8;
        soffA[hf] = (uint32_t)(row * ROWB + seg * 16);
    }
    // B fp32 staging: 128 rows x 128B = 1024 x 16B segs over 4 iterations
    size_t gaB[4];
    uint32_t soffB[4];
    #pragma unroll
    for (int q = 0; q < 4; q++) {
        int id = tid + q * 256;
        int row = id >> 3, seg = id & 7;
        gaB[q] = (size_t)(n0 + row) * Dn + seg * 4;      // float index
        soffB[q] = (uint32_t)(row * PB32ROW + seg * 16);
    }
    auto load_stage = [&](int c, int st) {
        const int kb = c * 32;
        const uint32_t sb = sbase + st * PSTG;
        #pragma unroll
        for (int hf = 0; hf < 2; hf++)
            cpa16(sb + soffA[hf], Ap + gaA[hf] + kb);
        #pragma unroll
        for (int q = 0; q < 4; q++)
            cpa16(sb + P_B32 + soffB[q], B32 + gaB[q] + kb);
        asm volatile("cp.async.commit_group;" ::: "memory");
    };
    // convert lane mapping: each thread converts 16 floats (half a row)
    const int cv_row = tid >> 1, cv_half = tid & 1;

    load_stage(0, 0);
    load_stage(1, 1);
    for (int c = 0; c < Dn / 32; c++) {
        const int st = c & 1;
        if (c + 1 < Dn / 32) asm volatile("cp.async.wait_group 1;" ::: "memory");
        else                 asm volatile("cp.async.wait_group 0;" ::: "memory");
        __syncthreads();
        // ---- fp32 -> fp16 convert (rides issue slack of the tensor-bound loop) ----
        {
            const float4* src = (const float4*)(smraw + (size_t)st * PSTG + P_B32 +
                                                cv_row * PB32ROW + cv_half * 64);
            uint32_t pk[8];
            #pragma unroll
            for (int i = 0; i < 4; i++) {
                float4 v = src[i];
                __half2 a = __floats2half2_rn(v.x, v.y);
                __half2 b = __floats2half2_rn(v.z, v.w);
                pk[2 * i] = *(uint32_t*)&a;
                pk[2 * i + 1] = *(uint32_t*)&b;
            }
            uint4* dst = (uint4*)(smraw + (size_t)st * PSTG + P_BF +
                                  cv_row * ROWB + cv_half * 32);
            dst[0] = make_uint4(pk[0], pk[1], pk[2], pk[3]);
            dst[1] = make_uint4(pk[4], pk[5], pk[6], pk[7]);
        }
        __syncthreads();
        const uint32_t sb = sbase + st * PSTG;
        #pragma unroll
        for (int k16 = 0; k16 < 32; k16 += 16) {
            uint32_t af[2][4];
            #pragma unroll
            for (int mi = 0; mi < 2; mi++) {
                uint32_t aoff = (uint32_t)((wm * 32 + mi * 16 + a_lr) * ROWB + (k16 + a_lc) * 2);
                ldsm4(af[mi], sb + aoff);
            }
            #pragma unroll
            for (int ng = 0; ng < 4; ng++) {
                uint32_t boff = (uint32_t)((wn * 64 + ng * 16 + b_nr) * ROWB + (k16 + b_kc) * 2);
                uint32_t bf[4];
                ldsm4(bf, sb + P_BF + boff);
                #pragma unroll
                for (int hv = 0; hv < 2; hv++) {
                    const int nj = ng * 2 + hv;
                    #pragma unroll
                    for (int mi = 0; mi < 2; mi++)
                        mma16816h(acc[mi][nj], af[mi], bf[2 * hv], bf[2 * hv + 1]);
                }
            }
        }
        __syncthreads();
        if (c + 2 < Dn / 32) load_stage(c + 2, st);
    }
    const int g = lane >> 2, t2 = (lane & 3) << 1;
    #pragma unroll
    for (int mi = 0; mi < 2; mi++) {
        #pragma unroll
        for (int nj = 0; nj < 8; nj++) {
            int r = m0 + wm * 32 + mi * 16 + g;
            int col = n0 + wn * 64 + nj * 8 + t2;
            *(float2*)&C[(size_t)r * Vn + col] = make_float2(acc[mi][nj][0], acc[mi][nj][1]);
            *(float2*)&C[(size_t)(r + 8) * Vn + col] = make_float2(acc[mi][nj][2], acc[mi][nj][3]);
        }
    }
}

// ---------------- launch ----------------
extern "C" void kernel_launch(void* const* d_in, const int* in_sizes, int n_in,
                              void* d_out, int out_size) {
    (void)in_sizes; (void)n_in; (void)out_size;
    const int*   ids    = (const int*)d_in[0];
    const float* embed  = (const float*)d_in[1];
    const float* router = (const float*)d_in[2];
    const float* w1     = (const float*)d_in[3];
    const float* w2     = (const float*)d_in[4];
    const float* lnw    = (const float*)d_in[5];
    float* out = (float*)d_out;

    float *hA, *hB;
    __half *pAp, *pw1p, *pw2p;
    __nv_bfloat16 *pAh, *pAl, *pw1h, *pw1l, *pw2h, *pw2l;
    cudaGetSymbolAddress((void**)&hA, g_hA);
    cudaGetSymbolAddress((void**)&hB, g_hB);
    cudaGetSymbolAddress((void**)&pAh, g_Ah);
    cudaGetSymbolAddress((void**)&pAl, g_Al);
    cudaGetSymbolAddress((void**)&pAp, g_Ap);
    cudaGetSymbolAddress((void**)&pw1h, g_w1h);
    cudaGetSymbolAddress((void**)&pw1l, g_w1l);
    cudaGetSymbolAddress((void**)&pw1p, g_w1p);
    cudaGetSymbolAddress((void**)&pw2h, g_w2h);
    cudaGetSymbolAddress((void**)&pw2l, g_w2l);
    cudaGetSymbolAddress((void**)&pw2p, g_w2p);

    static cudaStream_t s2 = nullptr;
    static cudaEvent_t evFork, evW1, evW2;
    if (!s2) {
        cudaStreamCreateWithFlags(&s2, cudaStreamNonBlocking);
        cudaEventCreateWithFlags(&evFork, cudaEventDisableTiming);
        cudaEventCreateWithFlags(&evW1, cudaEventDisableTiming);
        cudaEventCreateWithFlags(&evW2, cudaEventDisableTiming);
        cudaFuncSetAttribute(k_gemm1_hmma, cudaFuncAttributeMaxDynamicSharedMemorySize, 2 * STAGEB);
        cudaFuncSetAttribute(k_gemm2_hmma, cudaFuncAttributeMaxDynamicSharedMemorySize, 2 * STAGEB);
        cudaFuncSetAttribute(k_gemm1_fp16, cudaFuncAttributeMaxDynamicSharedMemorySize, 2 * STAGE2B);
        cudaFuncSetAttribute(k_gemm2_fp16, cudaFuncAttributeMaxDynamicSharedMemorySize, 2 * STAGE2B);
        cudaFuncSetAttribute(k_proj_fp16, cudaFuncAttributeMaxDynamicSharedMemorySize, 2 * PSTG);
    }

    // ---- fork: weight prep (w1/w2 each read once; three formats emitted) ----
    cudaEventRecord(evFork, 0);
    cudaStreamWaitEvent(s2, evFork, 0);
    k_tspl3<<<dim3(Fn / 32, Dn / 64, En), 256, 0, s2>>>(w1, pw1h, pw1l, pw1p, Dn, Fn);
    cudaEventRecord(evW1, s2);
    k_tspl3<<<dim3(Dn / 32, Fn / 64, En), 256, 0, s2>>>(w2, pw2h, pw2l, pw2p, Fn, Dn);
    cudaEventRecord(evW2, s2);

    // ---- main chain ----
    k_embed<<<(Tn * Dn / 4) / 256, 256>>>(ids, embed);

    float* hin = hA;
    float* hout = hB;
    for (int hop = 0; hop < 2; hop++) {
        k_router<<<Tn, 256>>>(hin, router + (size_t)hop * Dn * En);
        k_scan<<<1, 256>>>();
        k_prep_h<<<Tn, 256>>>(hin, hout, pAh, pAl, pAp, hop);
        if (hop == 0) {
            cudaStreamWaitEvent(0, evW1, 0);
            k_gemm1_hmma<<<dim3(Fn / 128, (CAPn + 127) / 128, En), 256, 2 * STAGEB>>>(pAh, pAl);
            cudaStreamWaitEvent(0, evW2, 0);
            k_gemm2_hmma<<<dim3(Dn / 128, (CAPn + 127) / 128, En), 256, 2 * STAGEB>>>(hout);
        } else {
            cudaStreamWaitEvent(0, evW1, 0);
            k_gemm1_fp16<<<dim3(Fn / 128, (CAPn + 127) / 128, En), 256, 2 * STAGE2B>>>(pAp);
            cudaStreamWaitEvent(0, evW2, 0);
            k_gemm2_fp16<<<dim3(Dn / 128, (CAPn + 127) / 128, En), 256, 2 * STAGE2B>>>(hout);
        }
        float* tmp = hin; hin = hout; hout = tmp;
    }
    k_rms_fp16<<<Tn, 256>>>(hin, lnw, pAp);

    k_proj_fp16<<<dim3(Tn / 128, Vn / 128), 256, 2 * PSTG>>>(pAp, embed, out);
}

// round 13
// speedup vs baseline: 1.0245x; 1.0245x over previous
#include <cuda_runtime.h>
#include <cuda_bf16.h>
#include <cuda_fp16.h>
#include <math.h>
#include <stdint.h>

#define Tn 2048
#define Dn 1024
#define En 8
#define Fn 2048
#define Vn 32000
#define CAPn 640

// ---------------- device scratch ----------------
__device__ float g_hA[Tn * Dn];
__device__ float g_hB[Tn * Dn];
__device__ int   g_top2[Tn * 2];
__device__ float g_topw[Tn * 2];
__device__ float g_wkept[Tn * 2];
__device__ int   g_elist[En * CAPn];
__device__ float g_ew[En * CAPn];
__device__ int   g_ecnt[En];
__device__ __half g_Bp[(size_t)Vn * Dn];
__device__ __nv_bfloat16 g_Ah[Tn * Dn];
__device__ __nv_bfloat16 g_Al[Tn * Dn];
__device__ __half g_Ap[Tn * Dn];
__device__ __nv_bfloat16 g_w1h[(size_t)En * Fn * Dn];
__device__ __nv_bfloat16 g_w1l[(size_t)En * Fn * Dn];
__device__ __half        g_w1p[(size_t)En * Fn * Dn];
__device__ __nv_bfloat16 g_w2h[(size_t)En * Dn * Fn];
__device__ __nv_bfloat16 g_w2l[(size_t)En * Dn * Fn];
__device__ __half        g_w2p[(size_t)En * Dn * Fn];
__device__ __nv_bfloat16 g_hidh[(size_t)En * CAPn * Fn];
__device__ __nv_bfloat16 g_hidl[(size_t)En * CAPn * Fn];
__device__ __half        g_hidp[(size_t)En * CAPn * Fn];

__device__ __forceinline__ float gelu_t(float x) {
    float u = 0.7978845608028654f * (x + 0.044715f * x * x * x);
    return 0.5f * x * (1.0f + tanhf(u));
}

// ---------------- hmma helpers ----------------
__device__ __forceinline__ uint32_t s2u(const void* p) {
    uint32_t a;
    asm("{ .reg .u64 t; cvta.to.shared.u64 t, %1; cvt.u32.u64 %0, t; }" : "=r"(a) : "l"(p));
    return a;
}
__device__ __forceinline__ void ldsm4(uint32_t* r, uint32_t a) {
    asm volatile("ldmatrix.sync.aligned.m8n8.x4.shared.b16 {%0,%1,%2,%3}, [%4];"
                 : "=r"(r[0]), "=r"(r[1]), "=r"(r[2]), "=r"(r[3]) : "r"(a));
}
__device__ __forceinline__ void mma16816(float* c, const uint32_t* a, uint32_t b0, uint32_t b1) {
    asm volatile("mma.sync.aligned.m16n8k16.row.col.f32.bf16.bf16.f32 "
                 "{%0,%1,%2,%3}, {%4,%5,%6,%7}, {%8,%9}, {%0,%1,%2,%3};"
                 : "+f"(c[0]), "+f"(c[1]), "+f"(c[2]), "+f"(c[3])
                 : "r"(a[0]), "r"(a[1]), "r"(a[2]), "r"(a[3]), "r"(b0), "r"(b1));
}
__device__ __forceinline__ void mma16816h(float* c, const uint32_t* a, uint32_t b0, uint32_t b1) {
    asm volatile("mma.sync.aligned.m16n8k16.row.col.f32.f16.f16.f32 "
                 "{%0,%1,%2,%3}, {%4,%5,%6,%7}, {%8,%9}, {%0,%1,%2,%3};"
                 : "+f"(c[0]), "+f"(c[1]), "+f"(c[2]), "+f"(c[3])
                 : "r"(a[0]), "r"(a[1]), "r"(a[2]), "r"(a[3]), "r"(b0), "r"(b1));
}
__device__ __forceinline__ void cpa16(uint32_t dst, const void* src) {
    asm volatile("cp.async.cg.shared.global [%0], [%1], 16;" :: "r"(dst), "l"(src) : "memory");
}
__device__ __forceinline__ void bsplit(float x, unsigned short& h, unsigned short& l) {
    __nv_bfloat16 hb = __float2bfloat16_rn(x);
    __nv_bfloat16 lb = __float2bfloat16_rn(x - __bfloat162float(hb));
    h = *(unsigned short*)&hb;
    l = *(unsigned short*)&lb;
}

// ---------------- embedding gather ----------------
__global__ void k_embed(const int* __restrict__ ids, const float* __restrict__ ew) {
    int i = blockIdx.x * blockDim.x + threadIdx.x;
    int t = i / (Dn / 4);
    int d4 = i % (Dn / 4);
    float4 v = ((const float4*)(ew + (size_t)ids[t] * Dn))[d4];
    ((float4*)(g_hA + (size_t)t * Dn))[d4] = v;
}

// ---------------- fp32 -> fp16 convert ----------------
__global__ void k_cvt16(const float* __restrict__ src, __half* __restrict__ dst, int n4) {
    int i = blockIdx.x * blockDim.x + threadIdx.x;
    if (i >= n4) return;
    float4 v = ((const float4*)src)[i];
    __half2 a = __floats2half2_rn(v.x, v.y);
    __half2 b = __floats2half2_rn(v.z, v.w);
    ((uint2*)dst)[i] = make_uint2(*(uint32_t*)&a, *(uint32_t*)&b);
}

// ---------------- fused per-hop h prep ----------------
__global__ void k_prep_h(const float* __restrict__ hin, float* __restrict__ hout,
                         __nv_bfloat16* __restrict__ hi, __nv_bfloat16* __restrict__ lo,
                         __half* __restrict__ fp, int mode) {
    int t = blockIdx.x;
    int i = (size_t)t * (Dn / 4) + threadIdx.x;
    float4 v = ((const float4*)hin)[i];
    if (mode == 0) {
        float x[4] = {v.x, v.y, v.z, v.w};
        unsigned short h[4], l[4];
        #pragma unroll
        for (int j = 0; j < 4; j++) bsplit(x[j], h[j], l[j]);
        ((uint2*)hi)[i] = make_uint2((uint32_t)h[0] | ((uint32_t)h[1] << 16),
                                     (uint32_t)h[2] | ((uint32_t)h[3] << 16));
        ((uint2*)lo)[i] = make_uint2((uint32_t)l[0] | ((uint32_t)l[1] << 16),
                                     (uint32_t)l[2] | ((uint32_t)l[3] << 16));
    } else {
        __half2 a = __floats2half2_rn(v.x, v.y);
        __half2 b = __floats2half2_rn(v.z, v.w);
        ((uint2*)fp)[i] = make_uint2(*(uint32_t*)&a, *(uint32_t*)&b);
    }
    float s = 1.0f - (g_wkept[2 * t] + g_wkept[2 * t + 1]);
    v.x *= s; v.y *= s; v.z *= s; v.w *= s;
    ((float4*)hout)[i] = v;
}

// ---------------- fused transpose+split: fp32 [E][R][C] -> bf16 hi/lo + fp16 [E][C][R] ----------------
__global__ void k_tspl3(const float* __restrict__ src, __nv_bfloat16* __restrict__ hi,
                        __nv_bfloat16* __restrict__ lo, __half* __restrict__ fp,
                        int R, int C) {
    __shared__ float t[64][33];
    int e = blockIdx.z;
    const float* S = src + (size_t)e * R * C;
    __nv_bfloat16* H = hi + (size_t)e * R * C;
    __nv_bfloat16* L = lo + (size_t)e * R * C;
    __half* P = fp + (size_t)e * R * C;
    int c0 = blockIdx.x * 32, r0 = blockIdx.y * 64;
    int tx = threadIdx.x & 31, ty = threadIdx.x >> 5;
    #pragma unroll
    for (int j = 0; j < 8; j++)
        t[ty + j * 8][tx] = S[(size_t)(r0 + ty + j * 8) * C + c0 + tx];
    __syncthreads();
    int c = threadIdx.x >> 3, ri = threadIdx.x & 7;
    unsigned short hb[8], lb[8];
    uint32_t pk[4];
    #pragma unroll
    for (int i = 0; i < 8; i++) bsplit(t[ri * 8 + i][c], hb[i], lb[i]);
    #pragma unroll
    for (int i = 0; i < 4; i++) {
        __half2 p = __floats2half2_rn(t[ri * 8 + 2 * i][c], t[ri * 8 + 2 * i + 1][c]);
        pk[i] = *(uint32_t*)&p;
    }
    size_t o = (size_t)(c0 + c) * R + r0 + ri * 8;
    *(uint4*)&H[o] = make_uint4((uint32_t)hb[0] | ((uint32_t)hb[1] << 16),
                                (uint32_t)hb[2] | ((uint32_t)hb[3] << 16),
                                (uint32_t)hb[4] | ((uint32_t)hb[5] << 16),
                                (uint32_t)hb[6] | ((uint32_t)hb[7] << 16));
    *(uint4*)&L[o] = make_uint4((uint32_t)lb[0] | ((uint32_t)lb[1] << 16),
                                (uint32_t)lb[2] | ((uint32_t)lb[3] << 16),
                                (uint32_t)lb[4] | ((uint32_t)lb[5] << 16),
                                (uint32_t)lb[6] | ((uint32_t)lb[7] << 16));
    *(uint4*)&P[o] = make_uint4(pk[0], pk[1], pk[2], pk[3]);
}

// ---------------- router ----------------
__global__ void k_router(const float* __restrict__ h, const float* __restrict__ rw) {
    int t = blockIdx.x;
    int lane = threadIdx.x & 31;
    int w = threadIdx.x >> 5;
    const float* hr = h + (size_t)t * Dn;
    float acc = 0.f;
    for (int d = lane; d < Dn; d += 32) acc += hr[d] * rw[d * En + w];
    #pragma unroll
    for (int o = 16; o; o >>= 1) acc += __shfl_xor_sync(0xFFFFFFFFu, acc, o);
    __shared__ float lg[En];
    if (lane == 0) lg[w] = acc;
    __syncthreads();
    if (threadIdx.x == 0) {
        float l[En];
        #pragma unroll
        for (int e = 0; e < En; e++) l[e] = lg[e];
        float m = l[0];
        #pragma unroll
        for (int e = 1; e < En; e++) m = fmaxf(m, l[e]);
        float p[En], s = 0.f;
        #pragma unroll
        for (int e = 0; e < En; e++) { p[e] = expf(l[e] - m); s += p[e]; }
        float inv = 1.0f / s;
        int i0 = 0;
        #pragma unroll
        for (int e = 1; e < En; e++) if (l[e] > l[i0]) i0 = e;
        int i1 = -1;
        #pragma unroll
        for (int e = 0; e < En; e++) {
            if (e == i0) continue;
            if (i1 < 0 || l[e] > l[i1]) i1 = e;
        }
        g_top2[2 * t] = i0;
        g_top2[2 * t + 1] = i1;
        g_topw[2 * t] = p[i0] * inv;
        g_topw[2 * t + 1] = p[i1] * inv;
        g_wkept[2 * t] = 0.f;
        g_wkept[2 * t + 1] = 0.f;
    }
}

// ---------------- capacity scan ----------------
__global__ void k_scan() {
    __shared__ int s_top[Tn * 2];
    for (int i = threadIdx.x; i < Tn * 2; i += 256) s_top[i] = g_top2[i];
    __syncthreads();
    int lane = threadIdx.x & 31;
    int e = threadIdx.x >> 5;
    if (e >= En) return;
    int base = 0;
    for (int t0 = 0; t0 < Tn; t0 += 32) {
        int t = t0 + lane;
        int a = s_top[2 * t], b = s_top[2 * t + 1];
        int j = (a == e) ? 0 : ((b == e) ? 1 : -1);
        unsigned bal = __ballot_sync(0xFFFFFFFFu, j >= 0);
        int rank = base + __popc(bal & (0xFFFFFFFFu >> (31 - lane)));
        if (j >= 0 && rank <= CAPn) {
            int slot = rank - 1;
            g_elist[e * CAPn + slot] = t;
            float wv = g_topw[2 * t + j];
            g_ew[e * CAPn + slot] = wv;
            g_wkept[2 * t + j] = wv;
        }
        base += __popc(bal);
    }
    if (lane == 0) g_ecnt[e] = base < CAPn ? base : CAPn;
}

// ---------------- fused final rmsnorm -> fp16 ----------------
__global__ void k_rms_fp16(const float* __restrict__ hin, const float* __restrict__ lnw,
                           __half* __restrict__ Ap) {
    int t = blockIdx.x;
    int lane = threadIdx.x & 31, wid = threadIdx.x >> 5;
    float4 v = ((const float4*)(hin + (size_t)t * Dn))[threadIdx.x];
    float s = v.x * v.x + v.y * v.y + v.z * v.z + v.w * v.w;
    #pragma unroll
    for (int o = 16; o; o >>= 1) s += __shfl_xor_sync(0xFFFFFFFFu, s, o);
    __shared__ float red[8];
    if (lane == 0) red[wid] = s;
    __syncthreads();
    float tot = 0.f;
    #pragma unroll
    for (int i = 0; i < 8; i++) tot += red[i];
    float sc = rsqrtf(tot * (1.0f / Dn) + 1e-6f);
    float4 w = ((const float4*)lnw)[threadIdx.x];
    __half2 a = __floats2half2_rn(v.x * sc * w.x, v.y * sc * w.y);
    __half2 b = __floats2half2_rn(v.z * sc * w.z, v.w * sc * w.w);
    ((uint2*)(Ap + (size_t)t * Dn))[threadIdx.x] = make_uint2(*(uint32_t*)&a, *(uint32_t*)&b);
}

// ================= HMMA tile framework (128x128, proven config) =================
#define ROWB 80
#define ARRB (128 * ROWB)
#define STAGEB (4 * ARRB)
#define STAGE2B (2 * ARRB)

#define HMMA_PROLOG \
    extern __shared__ char smraw[]; \
    const uint32_t sbase = s2u(smraw); \
    const int tid = threadIdx.x; \
    const int lane = tid & 31; \
    const int wm = (tid >> 5) & 3; \
    const int wn = tid >> 7; \
    float acc[2][8][4]; \
    _Pragma("unroll") for (int i = 0; i < 2; i++) \
        _Pragma("unroll") for (int j = 0; j < 8; j++) \
            _Pragma("unroll") for (int q = 0; q < 4; q++) acc[i][j][q] = 0.f; \
    const int a_lr = lane & 15; \
    const int a_lc = ((lane >> 4) << 3); \
    const int b_nr = ((lane >> 4) << 3) + (lane & 7); \
    const int b_kc = (lane & 8);

#define HMMA_MAINLOOP(NCHKv) \
    load_stage(0, 0); \
    load_stage(1, 1); \
    for (int c = 0; c < (NCHKv); c++) { \
        const int st = c & 1; \
        if (c + 1 < (NCHKv)) asm volatile("cp.async.wait_group 1;" ::: "memory"); \
        else                 asm volatile("cp.async.wait_group 0;" ::: "memory"); \
        __syncthreads(); \
        const uint32_t sb = sbase + st * STAGEB; \
        _Pragma("unroll") \
        for (int k16 = 0; k16 < 32; k16 += 16) { \
            uint32_t ah[2][4], al[2][4]; \
            _Pragma("unroll") \
            for (int mi = 0; mi < 2; mi++) { \
                uint32_t aoff = (uint32_t)((wm * 32 + mi * 16 + a_lr) * ROWB + (k16 + a_lc) * 2); \
                ldsm4(ah[mi], sb + aoff); \
                ldsm4(al[mi], sb + ARRB + aoff); \
            } \
            _Pragma("unroll") \
            for (int ng = 0; ng < 4; ng++) { \
                uint32_t boff = (uint32_t)((wn * 64 + ng * 16 + b_nr) * ROWB + (k16 + b_kc) * 2); \
                uint32_t bh[4], bl[4]; \
                ldsm4(bh, sb + 2 * ARRB + boff); \
                ldsm4(bl, sb + 3 * ARRB + boff); \
                _Pragma("unroll") \
                for (int hv = 0; hv < 2; hv++) { \
                    const int nj = ng * 2 + hv; \
                    _Pragma("unroll") \
                    for (int mi = 0; mi < 2; mi++) { \
                        mma16816(acc[mi][nj], ah[mi], bh[2 * hv], bh[2 * hv + 1]); \
                        mma16816(acc[mi][nj], al[mi], bh[2 * hv], bh[2 * hv + 1]); \
                        mma16816(acc[mi][nj], ah[mi], bl[2 * hv], bl[2 * hv + 1]); \
                    } \
                } \
            } \
        } \
        __syncthreads(); \
        if (c + 2 < (NCHKv)) load_stage(c + 2, st); \
    }

#define HMMA16_MAINLOOP(NCHKv) \
    load_stage(0, 0); \
    load_stage(1, 1); \
    for (int c = 0; c < (NCHKv); c++) { \
        const int st = c & 1; \
        if (c + 1 < (NCHKv)) asm volatile("cp.async.wait_group 1;" ::: "memory"); \
        else                 asm volatile("cp.async.wait_group 0;" ::: "memory"); \
        __syncthreads(); \
        const uint32_t sb = sbase + st * STAGE2B; \
        _Pragma("unroll") \
        for (int k16 = 0; k16 < 32; k16 += 16) { \
            uint32_t af[2][4]; \
            _Pragma("unroll") \
            for (int mi = 0; mi < 2; mi++) { \
                uint32_t aoff = (uint32_t)((wm * 32 + mi * 16 + a_lr) * ROWB + (k16 + a_lc) * 2); \
                ldsm4(af[mi], sb + aoff); \
            } \
            _Pragma("unroll") \
            for (int ng = 0; ng < 4; ng++) { \
                uint32_t boff = (uint32_t)((wn * 64 + ng * 16 + b_nr) * ROWB + (k16 + b_kc) * 2); \
                uint32_t bf[4]; \
                ldsm4(bf, sb + ARRB + boff); \
                _Pragma("unroll") \
                for (int hv = 0; hv < 2; hv++) { \
                    const int nj = ng * 2 + hv; \
                    _Pragma("unroll") \
                    for (int mi = 0; mi < 2; mi++) \
                        mma16816h(acc[mi][nj], af[mi], bf[2 * hv], bf[2 * hv + 1]); \
                } \
            } \
        } \
        __syncthreads(); \
        if (c + 2 < (NCHKv)) load_stage(c + 2, st); \
    }

// ---------------- hop-1 GEMM1 (bf16 3-term) ----------------
__global__ __launch_bounds__(256, 2)
void k_gemm1_hmma(const __nv_bfloat16* __restrict__ Ah, const __nv_bfloat16* __restrict__ Al) {
    const int e = blockIdx.z;
    const int cnt = g_ecnt[e];
    const int m0 = blockIdx.y * 128;
    if (m0 >= cnt) return;
    HMMA_PROLOG
    const int n0 = blockIdx.x * 128;
    const __nv_bfloat16* Wh = g_w1h + (size_t)e * Fn * Dn;
    const __nv_bfloat16* Wl = g_w1l + (size_t)e * Fn * Dn;
    size_t gaA[2], gaB[2];
    uint32_t soff[2];
    #pragma unroll
    for (int hf = 0; hf < 2; hf++) {
        int id = tid + hf * 256;
        int row = id >> 2, seg = id & 3;
        int mrow = m0 + row;
        if (mrow >= cnt) mrow = cnt - 1;
        int tok = g_elist[e * CAPn + mrow];
        gaA[hf] = (size_t)tok * Dn + seg * 8;
        gaB[hf] = (size_t)(n0 + row) * Dn + seg * 8;
        soff[hf] = (uint32_t)(row * ROWB + seg * 16);
    }
    auto load_stage = [&](int c, int st) {
        const int kb = c * 32;
        const uint32_t sb = sbase + st * STAGEB;
        #pragma unroll
        for (int hf = 0; hf < 2; hf++) {
            cpa16(sb + soff[hf], Ah + gaA[hf] + kb);
            cpa16(sb + ARRB + soff[hf], Al + gaA[hf] + kb);
            cpa16(sb + 2 * ARRB + soff[hf], Wh + gaB[hf] + kb);
            cpa16(sb + 3 * ARRB + soff[hf], Wl + gaB[hf] + kb);
        }
        asm volatile("cp.async.commit_group;" ::: "memory");
    };
    HMMA_MAINLOOP(Dn / 32)
    __nv_bfloat16* Hh = g_hidh + (size_t)e * CAPn * Fn;
    __nv_bfloat16* Hl = g_hidl + (size_t)e * CAPn * Fn;
    const int g = lane >> 2, t2 = (lane & 3) << 1;
    #pragma unroll
    for (int mi = 0; mi < 2; mi++) {
        int r = wm * 32 + mi * 16 + g;
        #pragma unroll
        for (int nj = 0; nj < 8; nj++) {
            int col = n0 + wn * 64 + nj * 8 + t2;
            int s0 = m0 + r, s1 = m0 + r + 8;
            if (s0 < cnt) {
                float x0 = gelu_t(acc[mi][nj][0]), x1 = gelu_t(acc[mi][nj][1]);
                unsigned short h0, l0, h1, l1;
                bsplit(x0, h0, l0);
                bsplit(x1, h1, l1);
                *(uint32_t*)&Hh[(size_t)s0 * Fn + col] = (uint32_t)h0 | ((uint32_t)h1 << 16);
                *(uint32_t*)&Hl[(size_t)s0 * Fn + col] = (uint32_t)l0 | ((uint32_t)l1 << 16);
            }
            if (s1 < cnt) {
                float x2 = gelu_t(acc[mi][nj][2]), x3 = gelu_t(acc[mi][nj][3]);
                unsigned short h2, l2, h3, l3;
                bsplit(x2, h2, l2);
                bsplit(x3, h3, l3);
                *(uint32_t*)&Hh[(size_t)s1 * Fn + col] = (uint32_t)h2 | ((uint32_t)h3 << 16);
                *(uint32_t*)&Hl[(size_t)s1 * Fn + col] = (uint32_t)l2 | ((uint32_t)l3 << 16);
            }
        }
    }
}

// ---------------- hop-1 GEMM2 (bf16 3-term, K-split x2): scatter ----------------
__global__ __launch_bounds__(256, 2)
void k_gemm2_hmma(float* __restrict__ hout) {
    const int e = blockIdx.z;
    const int cnt = g_ecnt[e];
    const int m0 = blockIdx.y * 128;
    if (m0 >= cnt) return;
    HMMA_PROLOG
    const int n0 = (blockIdx.x >> 1) * 128;
    const int kbase = (blockIdx.x & 1) * (Fn / 2);
    const __nv_bfloat16* Ahp = g_hidh + (size_t)e * CAPn * Fn;
    const __nv_bfloat16* Alp = g_hidl + (size_t)e * CAPn * Fn;
    const __nv_bfloat16* Wh = g_w2h + (size_t)e * Dn * Fn;
    const __nv_bfloat16* Wl = g_w2l + (size_t)e * Dn * Fn;
    size_t gaA[2], gaB[2];
    uint32_t soff[2];
    #pragma unroll
    for (int hf = 0; hf < 2; hf++) {
        int id = tid + hf * 256;
        int row = id >> 2, seg = id & 3;
        gaA[hf] = (size_t)(m0 + row) * Fn + kbase + seg * 8;
        gaB[hf] = (size_t)(n0 + row) * Fn + kbase + seg * 8;
        soff[hf] = (uint32_t)(row * ROWB + seg * 16);
    }
    auto load_stage = [&](int c, int st) {
        const int kb = c * 32;
        const uint32_t sb = sbase + st * STAGEB;
        #pragma unroll
        for (int hf = 0; hf < 2; hf++) {
            cpa16(sb + soff[hf], Ahp + gaA[hf] + kb);
            cpa16(sb + ARRB + soff[hf], Alp + gaA[hf] + kb);
            cpa16(sb + 2 * ARRB + soff[hf], Wh + gaB[hf] + kb);
            cpa16(sb + 3 * ARRB + soff[hf], Wl + gaB[hf] + kb);
        }
        asm volatile("cp.async.commit_group;" ::: "memory");
    };
    HMMA_MAINLOOP(Fn / 64)
    const int g = lane >> 2, t2 = (lane & 3) << 1;
    #pragma unroll
    for (int mi = 0; mi < 2; mi++) {
        int r = wm * 32 + mi * 16 + g;
        int s0 = m0 + r, s1 = m0 + r + 8;
        int tok0 = 0, tok1 = 0;
        float w0 = 0.f, w1v = 0.f;
        if (s0 < cnt) { tok0 = g_elist[e * CAPn + s0]; w0 = g_ew[e * CAPn + s0]; }
        if (s1 < cnt) { tok1 = g_elist[e * CAPn + s1]; w1v = g_ew[e * CAPn + s1]; }
        #pragma unroll
        for (int nj = 0; nj < 8; nj++) {
            int col = n0 + wn * 64 + nj * 8 + t2;
            if (s0 < cnt) {
                atomicAdd(&hout[(size_t)tok0 * Dn + col], w0 * acc[mi][nj][0]);
                atomicAdd(&hout[(size_t)tok0 * Dn + col + 1], w0 * acc[mi][nj][1]);
            }
            if (s1 < cnt) {
                atomicAdd(&hout[(size_t)tok1 * Dn + col], w1v * acc[mi][nj][2]);
                atomicAdd(&hout[(size_t)tok1 * Dn + col + 1], w1v * acc[mi][nj][3]);
            }
        }
    }
}

// ---------------- hop-2 GEMM1 (fp16 single) ----------------
__global__ __launch_bounds__(256, 2)
void k_gemm1_fp16(const __half* __restrict__ Ap) {
    const int e = blockIdx.z;
    const int cnt = g_ecnt[e];
    const int m0 = blockIdx.y * 128;
    if (m0 >= cnt) return;
    HMMA_PROLOG
    const int n0 = blockIdx.x * 128;
    const __half* Wp = g_w1p + (size_t)e * Fn * Dn;
    size_t gaA[2], gaB[2];
    uint32_t soff[2];
    #pragma unroll
    for (int hf = 0; hf < 2; hf++) {
        int id = tid + hf * 256;
        int row = id >> 2, seg = id & 3;
        int mrow = m0 + row;
        if (mrow >= cnt) mrow = cnt - 1;
        int tok = g_elist[e * CAPn + mrow];
        gaA[hf] = (size_t)tok * Dn + seg * 8;
        gaB[hf] = (size_t)(n0 + row) * Dn + seg * 8;
        soff[hf] = (uint32_t)(row * ROWB + seg * 16);
    }
    auto load_stage = [&](int c, int st) {
        const int kb = c * 32;
        const uint32_t sb = sbase + st * STAGE2B;
        #pragma unroll
        for (int hf = 0; hf < 2; hf++) {
            cpa16(sb + soff[hf], Ap + gaA[hf] + kb);
            cpa16(sb + ARRB + soff[hf], Wp + gaB[hf] + kb);
        }
        asm volatile("cp.async.commit_group;" ::: "memory");
    };
    HMMA16_MAINLOOP(Dn / 32)
    __half* Hp = g_hidp + (size_t)e * CAPn * Fn;
    const int g = lane >> 2, t2 = (lane & 3) << 1;
    #pragma unroll
    for (int mi = 0; mi < 2; mi++) {
        int r = wm * 32 + mi * 16 + g;
        #pragma unroll
        for (int nj = 0; nj < 8; nj++) {
            int col = n0 + wn * 64 + nj * 8 + t2;
            int s0 = m0 + r, s1 = m0 + r + 8;
            if (s0 < cnt) {
                __half2 p = __floats2half2_rn(gelu_t(acc[mi][nj][0]), gelu_t(acc[mi][nj][1]));
                *(uint32_t*)&Hp[(size_t)s0 * Fn + col] = *(uint32_t*)&p;
            }
            if (s1 < cnt) {
                __half2 p = __floats2half2_rn(gelu_t(acc[mi][nj][2]), gelu_t(acc[mi][nj][3]));
                *(uint32_t*)&Hp[(size_t)s1 * Fn + col] = *(uint32_t*)&p;
            }
        }
    }
}

// ---------------- hop-2 GEMM2 (fp16 single, K-split x2): scatter ----------------
__global__ __launch_bounds__(256, 2)
void k_gemm2_fp16(float* __restrict__ hout) {
    const int e = blockIdx.z;
    const int cnt = g_ecnt[e];
    const int m0 = blockIdx.y * 128;
    if (m0 >= cnt) return;
    HMMA_PROLOG
    const int n0 = (blockIdx.x >> 1) * 128;
    const int kbase = (blockIdx.x & 1) * (Fn / 2);
    const __half* Apx = g_hidp + (size_t)e * CAPn * Fn;
    const __half* Wp = g_w2p + (size_t)e * Dn * Fn;
    size_t gaA[2], gaB[2];
    uint32_t soff[2];
    #pragma unroll
    for (int hf = 0; hf < 2; hf++) {
        int id = tid + hf * 256;
        int row = id >> 2, seg = id & 3;
        gaA[hf] = (size_t)(m0 + row) * Fn + kbase + seg * 8;
        gaB[hf] = (size_t)(n0 + row) * Fn + kbase + seg * 8;
        soff[hf] = (uint32_t)(row * ROWB + seg * 16);
    }
    auto load_stage = [&](int c, int st) {
        const int kb = c * 32;
        const uint32_t sb = sbase + st * STAGE2B;
        #pragma unroll
        for (int hf = 0; hf < 2; hf++) {
            cpa16(sb + soff[hf], Apx + gaA[hf] + kb);
            cpa16(sb + ARRB + soff[hf], Wp + gaB[hf] + kb);
        }
        asm volatile("cp.async.commit_group;" ::: "memory");
    };
    HMMA16_MAINLOOP(Fn / 64)
    const int g = lane >> 2, t2 = (lane & 3) << 1;
    #pragma unroll
    for (int mi = 0; mi < 2; mi++) {
        int r = wm * 32 + mi * 16 + g;
        int s0 = m0 + r, s1 = m0 + r + 8;
        int tok0 = 0, tok1 = 0;
        float w0 = 0.f, w1v = 0.f;
        if (s0 < cnt) { tok0 = g_elist[e * CAPn + s0]; w0 = g_ew[e * CAPn + s0]; }
        if (s1 < cnt) { tok1 = g_elist[e * CAPn + s1]; w1v = g_ew[e * CAPn + s1]; }
        #pragma unroll
        for (int nj = 0; nj < 8; nj++) {
            int col = n0 + wn * 64 + nj * 8 + t2;
            if (s0 < cnt) {
                atomicAdd(&hout[(size_t)tok0 * Dn + col], w0 * acc[mi][nj][0]);
                atomicAdd(&hout[(size_t)tok0 * Dn + col + 1], w0 * acc[mi][nj][1]);
            }
            if (s1 < cnt) {
                atomicAdd(&hout[(size_t)tok1 * Dn + col], w1v * acc[mi][nj][2]);
                atomicAdd(&hout[(size_t)tok1 * Dn + col + 1], w1v * acc[mi][nj][3]);
            }
        }
    }
}

// ---------------- tied projection (fp16, 128x128, pre-converted B) ----------------
__global__ __launch_bounds__(256, 2)
void k_proj_fp16(const __half* __restrict__ Ap, const __half* __restrict__ Bp,
                 float* __restrict__ C) {
    HMMA_PROLOG
    const int m0 = blockIdx.x * 128;
    const int n0 = blockIdx.y * 128;
    size_t gaA[2], gaB[2];
    uint32_t soff[2];
    #pragma unroll
    for (int hf = 0; hf < 2; hf++) {
        int id = tid + hf * 256;
        int row = id >> 2, seg = id & 3;
        gaA[hf] = (size_t)(m0 + row) * Dn + seg * 8;
        gaB[hf] = (size_t)(n0 + row) * Dn + seg * 8;
        soff[hf] = (uint32_t)(row * ROWB + seg * 16);
    }
    auto load_stage = [&](int c, int st) {
        const int kb = c * 32;
        const uint32_t sb = sbase + st * STAGE2B;
        #pragma unroll
        for (int hf = 0; hf < 2; hf++) {
            cpa16(sb + soff[hf], Ap + gaA[hf] + kb);
            cpa16(sb + ARRB + soff[hf], Bp + gaB[hf] + kb);
        }
        asm volatile("cp.async.commit_group;" ::: "memory");
    };
    HMMA16_MAINLOOP(Dn / 32)
    const int g = lane >> 2, t2 = (lane & 3) << 1;
    #pragma unroll
    for (int mi = 0; mi < 2; mi++) {
        #pragma unroll
        for (int nj = 0; nj < 8; nj++) {
            int r = m0 + wm * 32 + mi * 16 + g;
            int col = n0 + wn * 64 + nj * 8 + t2;
            *(float2*)&C[(size_t)r * Vn + col] = make_float2(acc[mi][nj][0], acc[mi][nj][1]);
            *(float2*)&C[(size_t)(r + 8) * Vn + col] = make_float2(acc[mi][nj][2], acc[mi][nj][3]);
        }
    }
}

// ---------------- launch ----------------
extern "C" void kernel_launch(void* const* d_in, const int* in_sizes, int n_in,
                              void* d_out, int out_size) {
    (void)in_sizes; (void)n_in; (void)out_size;
    const int*   ids    = (const int*)d_in[0];
    const float* embed  = (const float*)d_in[1];
    const float* router = (const float*)d_in[2];
    const float* w1     = (const float*)d_in[3];
    const float* w2     = (const float*)d_in[4];
    const float* lnw    = (const float*)d_in[5];
    float* out = (float*)d_out;

    float *hA, *hB;
    __half *pBp, *pAp, *pw1p, *pw2p;
    __nv_bfloat16 *pAh, *pAl, *pw1h, *pw1l, *pw2h, *pw2l;
    cudaGetSymbolAddress((void**)&hA, g_hA);
    cudaGetSymbolAddress((void**)&hB, g_hB);
    cudaGetSymbolAddress((void**)&pBp, g_Bp);
    cudaGetSymbolAddress((void**)&pAh, g_Ah);
    cudaGetSymbolAddress((void**)&pAl, g_Al);
    cudaGetSymbolAddress((void**)&pAp, g_Ap);
    cudaGetSymbolAddress((void**)&pw1h, g_w1h);
    cudaGetSymbolAddress((void**)&pw1l, g_w1l);
    cudaGetSymbolAddress((void**)&pw1p, g_w1p);
    cudaGetSymbolAddress((void**)&pw2h, g_w2h);
    cudaGetSymbolAddress((void**)&pw2l, g_w2l);
    cudaGetSymbolAddress((void**)&pw2p, g_w2p);

    static cudaStream_t s2 = nullptr;
    static cudaEvent_t evFork, evW1, evW2, evBp;
    if (!s2) {
        cudaStreamCreateWithFlags(&s2, cudaStreamNonBlocking);
        cudaEventCreateWithFlags(&evFork, cudaEventDisableTiming);
        cudaEventCreateWithFlags(&evW1, cudaEventDisableTiming);
        cudaEventCreateWithFlags(&evW2, cudaEventDisableTiming);
        cudaEventCreateWithFlags(&evBp, cudaEventDisableTiming);
        cudaFuncSetAttribute(k_gemm1_hmma, cudaFuncAttributeMaxDynamicSharedMemorySize, 2 * STAGEB);
        cudaFuncSetAttribute(k_gemm2_hmma, cudaFuncAttributeMaxDynamicSharedMemorySize, 2 * STAGEB);
        cudaFuncSetAttribute(k_gemm1_fp16, cudaFuncAttributeMaxDynamicSharedMemorySize, 2 * STAGE2B);
        cudaFuncSetAttribute(k_gemm2_fp16, cudaFuncAttributeMaxDynamicSharedMemorySize, 2 * STAGE2B);
        cudaFuncSetAttribute(k_proj_fp16, cudaFuncAttributeMaxDynamicSharedMemorySize, 2 * STAGE2B);
    }

    // ---- fork: weight prep ----
    cudaEventRecord(evFork, 0);
    cudaStreamWaitEvent(s2, evFork, 0);
    k_tspl3<<<dim3(Fn / 32, Dn / 64, En), 256, 0, s2>>>(w1, pw1h, pw1l, pw1p, Dn, Fn);
    cudaEventRecord(evW1, s2);
    k_tspl3<<<dim3(Dn / 32, Fn / 64, En), 256, 0, s2>>>(w2, pw2h, pw2l, pw2p, Fn, Dn);
    cudaEventRecord(evW2, s2);
    k_cvt16<<<(Vn * Dn / 4 + 255) / 256, 256, 0, s2>>>(embed, pBp, Vn * Dn / 4);
    cudaEventRecord(evBp, s2);

    // ---- main chain ----
    k_embed<<<(Tn * Dn / 4) / 256, 256>>>(ids, embed);

    float* hin = hA;
    float* hout = hB;
    for (int hop = 0; hop < 2; hop++) {
        k_router<<<Tn, 256>>>(hin, router + (size_t)hop * Dn * En);
        k_scan<<<1, 256>>>();
        k_prep_h<<<Tn, 256>>>(hin, hout, pAh, pAl, pAp, hop);
        if (hop == 0) {
            cudaStreamWaitEvent(0, evW1, 0);
            k_gemm1_hmma<<<dim3(Fn / 128, (CAPn + 127) / 128, En), 256, 2 * STAGEB>>>(pAh, pAl);
            cudaStreamWaitEvent(0, evW2, 0);
            k_gemm2_hmma<<<dim3(Dn / 128 * 2, (CAPn + 127) / 128, En), 256, 2 * STAGEB>>>(hout);
        } else {
            cudaStreamWaitEvent(0, evW1, 0);
            k_gemm1_fp16<<<dim3(Fn / 128, (CAPn + 127) / 128, En), 256, 2 * STAGE2B>>>(pAp);
            cudaStreamWaitEvent(0, evW2, 0);
            k_gemm2_fp16<<<dim3(Dn / 128 * 2, (CAPn + 127) / 128, En), 256, 2 * STAGE2B>>>(hout);
        }
        float* tmp = hin; hin = hout; hout = tmp;
    }
    k_rms_fp16<<<Tn, 256>>>(hin, lnw, pAp);

    cudaStreamWaitEvent(0, evBp, 0);
    k_proj_fp16<<<dim3(Tn / 128, Vn / 128), 256, 2 * STAGE2B>>>(pAp, pBp, out);
}

// round 14
// speedup vs baseline: 1.0630x; 1.0376x over previous
#include <cuda_runtime.h>
#include <cuda_bf16.h>
#include <cuda_fp16.h>
#include <math.h>
#include <stdint.h>

#define Tn 2048
#define Dn 1024
#define En 8
#define Fn 2048
#define Vn 32000
#define CAPn 640

// ---------------- device scratch ----------------
__device__ float g_hA[Tn * Dn];
__device__ float g_hB[Tn * Dn];
__device__ int   g_top2[Tn * 2];
__device__ float g_topw[Tn * 2];
__device__ float g_wkept[Tn * 2];
__device__ int   g_elist[En * CAPn];
__device__ float g_ew[En * CAPn];
__device__ int   g_ecnt[En];
__device__ __half g_Bp[(size_t)Vn * Dn];
__device__ __nv_bfloat16 g_Ah[Tn * Dn];
__device__ __nv_bfloat16 g_Al[Tn * Dn];
__device__ __half g_Ap[Tn * Dn];
__device__ __nv_bfloat16 g_w1h[(size_t)En * Fn * Dn];
__device__ __nv_bfloat16 g_w1l[(size_t)En * Fn * Dn];
__device__ __half        g_w1p[(size_t)En * Fn * Dn];
__device__ __nv_bfloat16 g_w2h[(size_t)En * Dn * Fn];
__device__ __nv_bfloat16 g_w2l[(size_t)En * Dn * Fn];
__device__ __half        g_w2p[(size_t)En * Dn * Fn];
__device__ __nv_bfloat16 g_hidh[(size_t)En * CAPn * Fn];
__device__ __nv_bfloat16 g_hidl[(size_t)En * CAPn * Fn];
__device__ __half        g_hidp[(size_t)En * CAPn * Fn];

__device__ __forceinline__ float gelu_t(float x) {
    float u = 0.7978845608028654f * (x + 0.044715f * x * x * x);
    return 0.5f * x * (1.0f + tanhf(u));
}

// ---------------- hmma helpers ----------------
__device__ __forceinline__ uint32_t s2u(const void* p) {
    uint32_t a;
    asm("{ .reg .u64 t; cvta.to.shared.u64 t, %1; cvt.u32.u64 %0, t; }" : "=r"(a) : "l"(p));
    return a;
}
__device__ __forceinline__ void ldsm4(uint32_t* r, uint32_t a) {
    asm volatile("ldmatrix.sync.aligned.m8n8.x4.shared.b16 {%0,%1,%2,%3}, [%4];"
                 : "=r"(r[0]), "=r"(r[1]), "=r"(r[2]), "=r"(r[3]) : "r"(a));
}
__device__ __forceinline__ void mma16816(float* c, const uint32_t* a, uint32_t b0, uint32_t b1) {
    asm volatile("mma.sync.aligned.m16n8k16.row.col.f32.bf16.bf16.f32 "
                 "{%0,%1,%2,%3}, {%4,%5,%6,%7}, {%8,%9}, {%0,%1,%2,%3};"
                 : "+f"(c[0]), "+f"(c[1]), "+f"(c[2]), "+f"(c[3])
                 : "r"(a[0]), "r"(a[1]), "r"(a[2]), "r"(a[3]), "r"(b0), "r"(b1));
}
__device__ __forceinline__ void mma16816h(float* c, const uint32_t* a, uint32_t b0, uint32_t b1) {
    asm volatile("mma.sync.aligned.m16n8k16.row.col.f32.f16.f16.f32 "
                 "{%0,%1,%2,%3}, {%4,%5,%6,%7}, {%8,%9}, {%0,%1,%2,%3};"
                 : "+f"(c[0]), "+f"(c[1]), "+f"(c[2]), "+f"(c[3])
                 : "r"(a[0]), "r"(a[1]), "r"(a[2]), "r"(a[3]), "r"(b0), "r"(b1));
}
__device__ __forceinline__ void cpa16(uint32_t dst, const void* src) {
    asm volatile("cp.async.cg.shared.global [%0], [%1], 16;" :: "r"(dst), "l"(src) : "memory");
}
__device__ __forceinline__ void bsplit(float x, unsigned short& h, unsigned short& l) {
    __nv_bfloat16 hb = __float2bfloat16_rn(x);
    __nv_bfloat16 lb = __float2bfloat16_rn(x - __bfloat162float(hb));
    h = *(unsigned short*)&hb;
    l = *(unsigned short*)&lb;
}

// ---------------- embedding gather ----------------
__global__ void k_embed(const int* __restrict__ ids, const float* __restrict__ ew) {
    int i = blockIdx.x * blockDim.x + threadIdx.x;
    int t = i / (Dn / 4);
    int d4 = i % (Dn / 4);
    float4 v = ((const float4*)(ew + (size_t)ids[t] * Dn))[d4];
    ((float4*)(g_hA + (size_t)t * Dn))[d4] = v;
}

// ---------------- fp32 -> fp16 convert ----------------
__global__ void k_cvt16(const float* __restrict__ src, __half* __restrict__ dst, int n4) {
    int i = blockIdx.x * blockDim.x + threadIdx.x;
    if (i >= n4) return;
    float4 v = ((const float4*)src)[i];
    __half2 a = __floats2half2_rn(v.x, v.y);
    __half2 b = __floats2half2_rn(v.z, v.w);
    ((uint2*)dst)[i] = make_uint2(*(uint32_t*)&a, *(uint32_t*)&b);
}

// ---------------- fused per-hop h prep ----------------
__global__ void k_prep_h(const float* __restrict__ hin, float* __restrict__ hout,
                         __nv_bfloat16* __restrict__ hi, __nv_bfloat16* __restrict__ lo,
                         __half* __restrict__ fp, int mode) {
    int t = blockIdx.x;
    int i = (size_t)t * (Dn / 4) + threadIdx.x;
    float4 v = ((const float4*)hin)[i];
    if (mode == 0) {
        float x[4] = {v.x, v.y, v.z, v.w};
        unsigned short h[4], l[4];
        #pragma unroll
        for (int j = 0; j < 4; j++) bsplit(x[j], h[j], l[j]);
        ((uint2*)hi)[i] = make_uint2((uint32_t)h[0] | ((uint32_t)h[1] << 16),
                                     (uint32_t)h[2] | ((uint32_t)h[3] << 16));
        ((uint2*)lo)[i] = make_uint2((uint32_t)l[0] | ((uint32_t)l[1] << 16),
                                     (uint32_t)l[2] | ((uint32_t)l[3] << 16));
    } else {
        __half2 a = __floats2half2_rn(v.x, v.y);
        __half2 b = __floats2half2_rn(v.z, v.w);
        ((uint2*)fp)[i] = make_uint2(*(uint32_t*)&a, *(uint32_t*)&b);
    }
    float s = 1.0f - (g_wkept[2 * t] + g_wkept[2 * t + 1]);
    v.x *= s; v.y *= s; v.z *= s; v.w *= s;
    ((float4*)hout)[i] = v;
}

// ---------------- fused transpose+split: fp32 [E][R][C] -> bf16 hi/lo + fp16 [E][C][R] ----------------
__global__ void k_tspl3(const float* __restrict__ src, __nv_bfloat16* __restrict__ hi,
                        __nv_bfloat16* __restrict__ lo, __half* __restrict__ fp,
                        int R, int C) {
    __shared__ float t[64][33];
    int e = blockIdx.z;
    const float* S = src + (size_t)e * R * C;
    __nv_bfloat16* H = hi + (size_t)e * R * C;
    __nv_bfloat16* L = lo + (size_t)e * R * C;
    __half* P = fp + (size_t)e * R * C;
    int c0 = blockIdx.x * 32, r0 = blockIdx.y * 64;
    int tx = threadIdx.x & 31, ty = threadIdx.x >> 5;
    #pragma unroll
    for (int j = 0; j < 8; j++)
        t[ty + j * 8][tx] = S[(size_t)(r0 + ty + j * 8) * C + c0 + tx];
    __syncthreads();
    int c = threadIdx.x >> 3, ri = threadIdx.x & 7;
    unsigned short hb[8], lb[8];
    uint32_t pk[4];
    #pragma unroll
    for (int i = 0; i < 8; i++) bsplit(t[ri * 8 + i][c], hb[i], lb[i]);
    #pragma unroll
    for (int i = 0; i < 4; i++) {
        __half2 p = __floats2half2_rn(t[ri * 8 + 2 * i][c], t[ri * 8 + 2 * i + 1][c]);
        pk[i] = *(uint32_t*)&p;
    }
    size_t o = (size_t)(c0 + c) * R + r0 + ri * 8;
    *(uint4*)&H[o] = make_uint4((uint32_t)hb[0] | ((uint32_t)hb[1] << 16),
                                (uint32_t)hb[2] | ((uint32_t)hb[3] << 16),
                                (uint32_t)hb[4] | ((uint32_t)hb[5] << 16),
                                (uint32_t)hb[6] | ((uint32_t)hb[7] << 16));
    *(uint4*)&L[o] = make_uint4((uint32_t)lb[0] | ((uint32_t)lb[1] << 16),
                                (uint32_t)lb[2] | ((uint32_t)lb[3] << 16),
                                (uint32_t)lb[4] | ((uint32_t)lb[5] << 16),
                                (uint32_t)lb[6] | ((uint32_t)lb[7] << 16));
    *(uint4*)&P[o] = make_uint4(pk[0], pk[1], pk[2], pk[3]);
}

// ---------------- router v2: 8 tokens/block, smem-transposed weights ----------------
__global__ __launch_bounds__(256) void k_router2(const float* __restrict__ h,
                                                 const float* __restrict__ rw) {
    __shared__ float s_rw[En * Dn];              // [e][d], 32 KB
    const int tid = threadIdx.x;
    // load + transpose rw (global layout d*En+e): each float4 = 4 experts of one d
    #pragma unroll
    for (int k = 0; k < 8; k++) {
        int fidx = tid + 256 * k;                // 0..2047 float4s
        float4 v = ((const float4*)rw)[fidx];
        int d = fidx >> 1;
        int e0 = (fidx & 1) << 2;
        s_rw[(e0 + 0) * Dn + d] = v.x;
        s_rw[(e0 + 1) * Dn + d] = v.y;
        s_rw[(e0 + 2) * Dn + d] = v.z;
        s_rw[(e0 + 3) * Dn + d] = v.w;
    }
    __syncthreads();
    const int warp = tid >> 5, lane = tid & 31;
    const int t = blockIdx.x * 8 + warp;
    const float4* hr = (const float4*)(h + (size_t)t * Dn);
    float acc[En];
    #pragma unroll
    for (int e = 0; e < En; e++) acc[e] = 0.f;
    #pragma unroll
    for (int i = 0; i < 8; i++) {
        float4 hv = hr[i * 32 + lane];
        #pragma unroll
        for (int e = 0; e < En; e++) {
            float4 wv = ((const float4*)(s_rw + e * Dn))[i * 32 + lane];
            acc[e] += hv.x * wv.x + hv.y * wv.y + hv.z * wv.z + hv.w * wv.w;
        }
    }
    #pragma unroll
    for (int o = 16; o; o >>= 1)
        #pragma unroll
        for (int e = 0; e < En; e++) acc[e] += __shfl_xor_sync(0xFFFFFFFFu, acc[e], o);
    if (lane == 0) {
        float m = acc[0];
        #pragma unroll
        for (int e = 1; e < En; e++) m = fmaxf(m, acc[e]);
        float p[En], s = 0.f;
        #pragma unroll
        for (int e = 0; e < En; e++) { p[e] = expf(acc[e] - m); s += p[e]; }
        float inv = 1.0f / s;
        int i0 = 0;
        #pragma unroll
        for (int e = 1; e < En; e++) if (acc[e] > acc[i0]) i0 = e;
        int i1 = -1;
        #pragma unroll
        for (int e = 0; e < En; e++) {
            if (e == i0) continue;
            if (i1 < 0 || acc[e] > acc[i1]) i1 = e;
        }
        g_top2[2 * t] = i0;
        g_top2[2 * t + 1] = i1;
        g_topw[2 * t] = p[i0] * inv;
        g_topw[2 * t + 1] = p[i1] * inv;
        g_wkept[2 * t] = 0.f;
        g_wkept[2 * t + 1] = 0.f;
    }
}

// ---------------- capacity scan ----------------
__global__ void k_scan() {
    __shared__ int s_top[Tn * 2];
    for (int i = threadIdx.x; i < Tn * 2; i += 256) s_top[i] = g_top2[i];
    __syncthreads();
    int lane = threadIdx.x & 31;
    int e = threadIdx.x >> 5;
    if (e >= En) return;
    int base = 0;
    for (int t0 = 0; t0 < Tn; t0 += 32) {
        int t = t0 + lane;
        int a = s_top[2 * t], b = s_top[2 * t + 1];
        int j = (a == e) ? 0 : ((b == e) ? 1 : -1);
        unsigned bal = __ballot_sync(0xFFFFFFFFu, j >= 0);
        int rank = base + __popc(bal & (0xFFFFFFFFu >> (31 - lane)));
        if (j >= 0 && rank <= CAPn) {
            int slot = rank - 1;
            g_elist[e * CAPn + slot] = t;
            float wv = g_topw[2 * t + j];
            g_ew[e * CAPn + slot] = wv;
            g_wkept[2 * t + j] = wv;
        }
        base += __popc(bal);
    }
    if (lane == 0) g_ecnt[e] = base < CAPn ? base : CAPn;
}

// ---------------- fused final rmsnorm -> fp16 ----------------
__global__ void k_rms_fp16(const float* __restrict__ hin, const float* __restrict__ lnw,
                           __half* __restrict__ Ap) {
    int t = blockIdx.x;
    int lane = threadIdx.x & 31, wid = threadIdx.x >> 5;
    float4 v = ((const float4*)(hin + (size_t)t * Dn))[threadIdx.x];
    float s = v.x * v.x + v.y * v.y + v.z * v.z + v.w * v.w;
    #pragma unroll
    for (int o = 16; o; o >>= 1) s += __shfl_xor_sync(0xFFFFFFFFu, s, o);
    __shared__ float red[8];
    if (lane == 0) red[wid] = s;
    __syncthreads();
    float tot = 0.f;
    #pragma unroll
    for (int i = 0; i < 8; i++) tot += red[i];
    float sc = rsqrtf(tot * (1.0f / Dn) + 1e-6f);
    float4 w = ((const float4*)lnw)[threadIdx.x];
    __half2 a = __floats2half2_rn(v.x * sc * w.x, v.y * sc * w.y);
    __half2 b = __floats2half2_rn(v.z * sc * w.z, v.w * sc * w.w);
    ((uint2*)(Ap + (size_t)t * Dn))[threadIdx.x] = make_uint2(*(uint32_t*)&a, *(uint32_t*)&b);
}

// ================= HMMA tile framework (128x128, proven config) =================
#define ROWB 80
#define ARRB (128 * ROWB)
#define STAGEB (4 * ARRB)
#define STAGE2B (2 * ARRB)

#define HMMA_PROLOG \
    extern __shared__ char smraw[]; \
    const uint32_t sbase = s2u(smraw); \
    const int tid = threadIdx.x; \
    const int lane = tid & 31; \
    const int wm = (tid >> 5) & 3; \
    const int wn = tid >> 7; \
    float acc[2][8][4]; \
    _Pragma("unroll") for (int i = 0; i < 2; i++) \
        _Pragma("unroll") for (int j = 0; j < 8; j++) \
            _Pragma("unroll") for (int q = 0; q < 4; q++) acc[i][j][q] = 0.f; \
    const int a_lr = lane & 15; \
    const int a_lc = ((lane >> 4) << 3); \
    const int b_nr = ((lane >> 4) << 3) + (lane & 7); \
    const int b_kc = (lane & 8);

#define HMMA_MAINLOOP(NCHKv) \
    load_stage(0, 0); \
    load_stage(1, 1); \
    for (int c = 0; c < (NCHKv); c++) { \
        const int st = c & 1; \
        if (c + 1 < (NCHKv)) asm volatile("cp.async.wait_group 1;" ::: "memory"); \
        else                 asm volatile("cp.async.wait_group 0;" ::: "memory"); \
        __syncthreads(); \
        const uint32_t sb = sbase + st * STAGEB; \
        _Pragma("unroll") \
        for (int k16 = 0; k16 < 32; k16 += 16) { \
            uint32_t ah[2][4], al[2][4]; \
            _Pragma("unroll") \
            for (int mi = 0; mi < 2; mi++) { \
                uint32_t aoff = (uint32_t)((wm * 32 + mi * 16 + a_lr) * ROWB + (k16 + a_lc) * 2); \
                ldsm4(ah[mi], sb + aoff); \
                ldsm4(al[mi], sb + ARRB + aoff); \
            } \
            _Pragma("unroll") \
            for (int ng = 0; ng < 4; ng++) { \
                uint32_t boff = (uint32_t)((wn * 64 + ng * 16 + b_nr) * ROWB + (k16 + b_kc) * 2); \
                uint32_t bh[4], bl[4]; \
                ldsm4(bh, sb + 2 * ARRB + boff); \
                ldsm4(bl, sb + 3 * ARRB + boff); \
                _Pragma("unroll") \
                for (int hv = 0; hv < 2; hv++) { \
                    const int nj = ng * 2 + hv; \
                    _Pragma("unroll") \
                    for (int mi = 0; mi < 2; mi++) { \
                        mma16816(acc[mi][nj], ah[mi], bh[2 * hv], bh[2 * hv + 1]); \
                        mma16816(acc[mi][nj], al[mi], bh[2 * hv], bh[2 * hv + 1]); \
                        mma16816(acc[mi][nj], ah[mi], bl[2 * hv], bl[2 * hv + 1]); \
                    } \
                } \
            } \
        } \
        __syncthreads(); \
        if (c + 2 < (NCHKv)) load_stage(c + 2, st); \
    }

#define HMMA16_MAINLOOP(NCHKv) \
    load_stage(0, 0); \
    load_stage(1, 1); \
    for (int c = 0; c < (NCHKv); c++) { \
        const int st = c & 1; \
        if (c + 1 < (NCHKv)) asm volatile("cp.async.wait_group 1;" ::: "memory"); \
        else                 asm volatile("cp.async.wait_group 0;" ::: "memory"); \
        __syncthreads(); \
        const uint32_t sb = sbase + st * STAGE2B; \
        _Pragma("unroll") \
        for (int k16 = 0; k16 < 32; k16 += 16) { \
            uint32_t af[2][4]; \
            _Pragma("unroll") \
            for (int mi = 0; mi < 2; mi++) { \
                uint32_t aoff = (uint32_t)((wm * 32 + mi * 16 + a_lr) * ROWB + (k16 + a_lc) * 2); \
                ldsm4(af[mi], sb + aoff); \
            } \
            _Pragma("unroll") \
            for (int ng = 0; ng < 4; ng++) { \
                uint32_t boff = (uint32_t)((wn * 64 + ng * 16 + b_nr) * ROWB + (k16 + b_kc) * 2); \
                uint32_t bf[4]; \
                ldsm4(bf, sb + ARRB + boff); \
                _Pragma("unroll") \
                for (int hv = 0; hv < 2; hv++) { \
                    const int nj = ng * 2 + hv; \
                    _Pragma("unroll") \
                    for (int mi = 0; mi < 2; mi++) \
                        mma16816h(acc[mi][nj], af[mi], bf[2 * hv], bf[2 * hv + 1]); \
                } \
            } \
        } \
        __syncthreads(); \
        if (c + 2 < (NCHKv)) load_stage(c + 2, st); \
    }

// ---------------- hop-1 GEMM1 (bf16 3-term) ----------------
__global__ __launch_bounds__(256, 2)
void k_gemm1_hmma(const __nv_bfloat16* __restrict__ Ah, const __nv_bfloat16* __restrict__ Al) {
    const int e = blockIdx.z;
    const int cnt = g_ecnt[e];
    const int m0 = blockIdx.y * 128;
    if (m0 >= cnt) return;
    HMMA_PROLOG
    const int n0 = blockIdx.x * 128;
    const __nv_bfloat16* Wh = g_w1h + (size_t)e * Fn * Dn;
    const __nv_bfloat16* Wl = g_w1l + (size_t)e * Fn * Dn;
    size_t gaA[2], gaB[2];
    uint32_t soff[2];
    #pragma unroll
    for (int hf = 0; hf < 2; hf++) {
        int id = tid + hf * 256;
        int row = id >> 2, seg = id & 3;
        int mrow = m0 + row;
        if (mrow >= cnt) mrow = cnt - 1;
        int tok = g_elist[e * CAPn + mrow];
        gaA[hf] = (size_t)tok * Dn + seg * 8;
        gaB[hf] = (size_t)(n0 + row) * Dn + seg * 8;
        soff[hf] = (uint32_t)(row * ROWB + seg * 16);
    }
    auto load_stage = [&](int c, int st) {
        const int kb = c * 32;
        const uint32_t sb = sbase + st * STAGEB;
        #pragma unroll
        for (int hf = 0; hf < 2; hf++) {
            cpa16(sb + soff[hf], Ah + gaA[hf] + kb);
            cpa16(sb + ARRB + soff[hf], Al + gaA[hf] + kb);
            cpa16(sb + 2 * ARRB + soff[hf], Wh + gaB[hf] + kb);
            cpa16(sb + 3 * ARRB + soff[hf], Wl + gaB[hf] + kb);
        }
        asm volatile("cp.async.commit_group;" ::: "memory");
    };
    HMMA_MAINLOOP(Dn / 32)
    __nv_bfloat16* Hh = g_hidh + (size_t)e * CAPn * Fn;
    __nv_bfloat16* Hl = g_hidl + (size_t)e * CAPn * Fn;
    const int g = lane >> 2, t2 = (lane & 3) << 1;
    #pragma unroll
    for (int mi = 0; mi < 2; mi++) {
        int r = wm * 32 + mi * 16 + g;
        #pragma unroll
        for (int nj = 0; nj < 8; nj++) {
            int col = n0 + wn * 64 + nj * 8 + t2;
            int s0 = m0 + r, s1 = m0 + r + 8;
            if (s0 < cnt) {
                float x0 = gelu_t(acc[mi][nj][0]), x1 = gelu_t(acc[mi][nj][1]);
                unsigned short h0, l0, h1, l1;
                bsplit(x0, h0, l0);
                bsplit(x1, h1, l1);
                *(uint32_t*)&Hh[(size_t)s0 * Fn + col] = (uint32_t)h0 | ((uint32_t)h1 << 16);
                *(uint32_t*)&Hl[(size_t)s0 * Fn + col] = (uint32_t)l0 | ((uint32_t)l1 << 16);
            }
            if (s1 < cnt) {
                float x2 = gelu_t(acc[mi][nj][2]), x3 = gelu_t(acc[mi][nj][3]);
                unsigned short h2, l2, h3, l3;
                bsplit(x2, h2, l2);
                bsplit(x3, h3, l3);
                *(uint32_t*)&Hh[(size_t)s1 * Fn + col] = (uint32_t)h2 | ((uint32_t)h3 << 16);
                *(uint32_t*)&Hl[(size_t)s1 * Fn + col] = (uint32_t)l2 | ((uint32_t)l3 << 16);
            }
        }
    }
}

// ---------------- hop-1 GEMM2 (bf16 3-term, full K): scatter ----------------
__global__ __launch_bounds__(256, 2)
void k_gemm2_hmma(float* __restrict__ hout) {
    const int e = blockIdx.z;
    const int cnt = g_ecnt[e];
    const int m0 = blockIdx.y * 128;
    if (m0 >= cnt) return;
    HMMA_PROLOG
    const int n0 = blockIdx.x * 128;
    const __nv_bfloat16* Ahp = g_hidh + (size_t)e * CAPn * Fn;
    const __nv_bfloat16* Alp = g_hidl + (size_t)e * CAPn * Fn;
    const __nv_bfloat16* Wh = g_w2h + (size_t)e * Dn * Fn;
    const __nv_bfloat16* Wl = g_w2l + (size_t)e * Dn * Fn;
    size_t gaA[2], gaB[2];
    uint32_t soff[2];
    #pragma unroll
    for (int hf = 0; hf < 2; hf++) {
        int id = tid + hf * 256;
        int row = id >> 2, seg = id & 3;
        gaA[hf] = (size_t)(m0 + row) * Fn + seg * 8;
        gaB[hf] = (size_t)(n0 + row) * Fn + seg * 8;
        soff[hf] = (uint32_t)(row * ROWB + seg * 16);
    }
    auto load_stage = [&](int c, int st) {
        const int kb = c * 32;
        const uint32_t sb = sbase + st * STAGEB;
        #pragma unroll
        for (int hf = 0; hf < 2; hf++) {
            cpa16(sb + soff[hf], Ahp + gaA[hf] + kb);
            cpa16(sb + ARRB + soff[hf], Alp + gaA[hf] + kb);
            cpa16(sb + 2 * ARRB + soff[hf], Wh + gaB[hf] + kb);
            cpa16(sb + 3 * ARRB + soff[hf], Wl + gaB[hf] + kb);
        }
        asm volatile("cp.async.commit_group;" ::: "memory");
    };
    HMMA_MAINLOOP(Fn / 32)
    const int g = lane >> 2, t2 = (lane & 3) << 1;
    #pragma unroll
    for (int mi = 0; mi < 2; mi++) {
        int r = wm * 32 + mi * 16 + g;
        int s0 = m0 + r, s1 = m0 + r + 8;
        int tok0 = 0, tok1 = 0;
        float w0 = 0.f, w1v = 0.f;
        if (s0 < cnt) { tok0 = g_elist[e * CAPn + s0]; w0 = g_ew[e * CAPn + s0]; }
        if (s1 < cnt) { tok1 = g_elist[e * CAPn + s1]; w1v = g_ew[e * CAPn + s1]; }
        #pragma unroll
        for (int nj = 0; nj < 8; nj++) {
            int col = n0 + wn * 64 + nj * 8 + t2;
            if (s0 < cnt) {
                atomicAdd(&hout[(size_t)tok0 * Dn + col], w0 * acc[mi][nj][0]);
                atomicAdd(&hout[(size_t)tok0 * Dn + col + 1], w0 * acc[mi][nj][1]);
            }
            if (s1 < cnt) {
                atomicAdd(&hout[(size_t)tok1 * Dn + col], w1v * acc[mi][nj][2]);
                atomicAdd(&hout[(size_t)tok1 * Dn + col + 1], w1v * acc[mi][nj][3]);
            }
        }
    }
}

// ---------------- hop-2 GEMM1 (fp16 single) ----------------
__global__ __launch_bounds__(256, 2)
void k_gemm1_fp16(const __half* __restrict__ Ap) {
    const int e = blockIdx.z;
    const int cnt = g_ecnt[e];
    const int m0 = blockIdx.y * 128;
    if (m0 >= cnt) return;
    HMMA_PROLOG
    const int n0 = blockIdx.x * 128;
    const __half* Wp = g_w1p + (size_t)e * Fn * Dn;
    size_t gaA[2], gaB[2];
    uint32_t soff[2];
    #pragma unroll
    for (int hf = 0; hf < 2; hf++) {
        int id = tid + hf * 256;
        int row = id >> 2, seg = id & 3;
        int mrow = m0 + row;
        if (mrow >= cnt) mrow = cnt - 1;
        int tok = g_elist[e * CAPn + mrow];
        gaA[hf] = (size_t)tok * Dn + seg * 8;
        gaB[hf] = (size_t)(n0 + row) * Dn + seg * 8;
        soff[hf] = (uint32_t)(row * ROWB + seg * 16);
    }
    auto load_stage = [&](int c, int st) {
        const int kb = c * 32;
        const uint32_t sb = sbase + st * STAGE2B;
        #pragma unroll
        for (int hf = 0; hf < 2; hf++) {
            cpa16(sb + soff[hf], Ap + gaA[hf] + kb);
            cpa16(sb + ARRB + soff[hf], Wp + gaB[hf] + kb);
        }
        asm volatile("cp.async.commit_group;" ::: "memory");
    };
    HMMA16_MAINLOOP(Dn / 32)
    __half* Hp = g_hidp + (size_t)e * CAPn * Fn;
    const int g = lane >> 2, t2 = (lane & 3) << 1;
    #pragma unroll
    for (int mi = 0; mi < 2; mi++) {
        int r = wm * 32 + mi * 16 + g;
        #pragma unroll
        for (int nj = 0; nj < 8; nj++) {
            int col = n0 + wn * 64 + nj * 8 + t2;
            int s0 = m0 + r, s1 = m0 + r + 8;
            if (s0 < cnt) {
                __half2 p = __floats2half2_rn(gelu_t(acc[mi][nj][0]), gelu_t(acc[mi][nj][1]));
                *(uint32_t*)&Hp[(size_t)s0 * Fn + col] = *(uint32_t*)&p;
            }
            if (s1 < cnt) {
                __half2 p = __floats2half2_rn(gelu_t(acc[mi][nj][2]), gelu_t(acc[mi][nj][3]));
                *(uint32_t*)&Hp[(size_t)s1 * Fn + col] = *(uint32_t*)&p;
            }
        }
    }
}

// ---------------- hop-2 GEMM2 (fp16 single, full K): scatter ----------------
__global__ __launch_bounds__(256, 2)
void k_gemm2_fp16(float* __restrict__ hout) {
    const int e = blockIdx.z;
    const int cnt = g_ecnt[e];
    const int m0 = blockIdx.y * 128;
    if (m0 >= cnt) return;
    HMMA_PROLOG
    const int n0 = blockIdx.x * 128;
    const __half* Apx = g_hidp + (size_t)e * CAPn * Fn;
    const __half* Wp = g_w2p + (size_t)e * Dn * Fn;
    size_t gaA[2], gaB[2];
    uint32_t soff[2];
    #pragma unroll
    for (int hf = 0; hf < 2; hf++) {
        int id = tid + hf * 256;
        int row = id >> 2, seg = id & 3;
        gaA[hf] = (size_t)(m0 + row) * Fn + seg * 8;
        gaB[hf] = (size_t)(n0 + row) * Fn + seg * 8;
        soff[hf] = (uint32_t)(row * ROWB + seg * 16);
    }
    auto load_stage = [&](int c, int st) {
        const int kb = c * 32;
        const uint32_t sb = sbase + st * STAGE2B;
        #pragma unroll
        for (int hf = 0; hf < 2; hf++) {
            cpa16(sb + soff[hf], Apx + gaA[hf] + kb);
            cpa16(sb + ARRB + soff[hf], Wp + gaB[hf] + kb);
        }
        asm volatile("cp.async.commit_group;" ::: "memory");
    };
    HMMA16_MAINLOOP(Fn / 32)
    const int g = lane >> 2, t2 = (lane & 3) << 1;
    #pragma unroll
    for (int mi = 0; mi < 2; mi++) {
        int r = wm * 32 + mi * 16 + g;
        int s0 = m0 + r, s1 = m0 + r + 8;
        int tok0 = 0, tok1 = 0;
        float w0 = 0.f, w1v = 0.f;
        if (s0 < cnt) { tok0 = g_elist[e * CAPn + s0]; w0 = g_ew[e * CAPn + s0]; }
        if (s1 < cnt) { tok1 = g_elist[e * CAPn + s1]; w1v = g_ew[e * CAPn + s1]; }
        #pragma unroll
        for (int nj = 0; nj < 8; nj++) {
            int col = n0 + wn * 64 + nj * 8 + t2;
            if (s0 < cnt) {
                atomicAdd(&hout[(size_t)tok0 * Dn + col], w0 * acc[mi][nj][0]);
                atomicAdd(&hout[(size_t)tok0 * Dn + col + 1], w0 * acc[mi][nj][1]);
            }
            if (s1 < cnt) {
                atomicAdd(&hout[(size_t)tok1 * Dn + col], w1v * acc[mi][nj][2]);
                atomicAdd(&hout[(size_t)tok1 * Dn + col + 1], w1v * acc[mi][nj][3]);
            }
        }
    }
}

// ---------------- tied projection (fp16, 128x128, pre-converted B) ----------------
__global__ __launch_bounds__(256, 2)
void k_proj_fp16(const __half* __restrict__ Ap, const __half* __restrict__ Bp,
                 float* __restrict__ C) {
    HMMA_PROLOG
    const int m0 = blockIdx.x * 128;
    const int n0 = blockIdx.y * 128;
    size_t gaA[2], gaB[2];
    uint32_t soff[2];
    #pragma unroll
    for (int hf = 0; hf < 2; hf++) {
        int id = tid + hf * 256;
        int row = id >> 2, seg = id & 3;
        gaA[hf] = (size_t)(m0 + row) * Dn + seg * 8;
        gaB[hf] = (size_t)(n0 + row) * Dn + seg * 8;
        soff[hf] = (uint32_t)(row * ROWB + seg * 16);
    }
    auto load_stage = [&](int c, int st) {
        const int kb = c * 32;
        const uint32_t sb = sbase + st * STAGE2B;
        #pragma unroll
        for (int hf = 0; hf < 2; hf++) {
            cpa16(sb + soff[hf], Ap + gaA[hf] + kb);
            cpa16(sb + ARRB + soff[hf], Bp + gaB[hf] + kb);
        }
        asm volatile("cp.async.commit_group;" ::: "memory");
    };
    HMMA16_MAINLOOP(Dn / 32)
    const int g = lane >> 2, t2 = (lane & 3) << 1;
    #pragma unroll
    for (int mi = 0; mi < 2; mi++) {
        #pragma unroll
        for (int nj = 0; nj < 8; nj++) {
            int r = m0 + wm * 32 + mi * 16 + g;
            int col = n0 + wn * 64 + nj * 8 + t2;
            *(float2*)&C[(size_t)r * Vn + col] = make_float2(acc[mi][nj][0], acc[mi][nj][1]);
            *(float2*)&C[(size_t)(r + 8) * Vn + col] = make_float2(acc[mi][nj][2], acc[mi][nj][3]);
        }
    }
}

// ---------------- launch ----------------
extern "C" void kernel_launch(void* const* d_in, const int* in_sizes, int n_in,
                              void* d_out, int out_size) {
    (void)in_sizes; (void)n_in; (void)out_size;
    const int*   ids    = (const int*)d_in[0];
    const float* embed  = (const float*)d_in[1];
    const float* router = (const float*)d_in[2];
    const float* w1     = (const float*)d_in[3];
    const float* w2     = (const float*)d_in[4];
    const float* lnw    = (const float*)d_in[5];
    float* out = (float*)d_out;

    float *hA, *hB;
    __half *pBp, *pAp, *pw1p, *pw2p;
    __nv_bfloat16 *pAh, *pAl, *pw1h, *pw1l, *pw2h, *pw2l;
    cudaGetSymbolAddress((void**)&hA, g_hA);
    cudaGetSymbolAddress((void**)&hB, g_hB);
    cudaGetSymbolAddress((void**)&pBp, g_Bp);
    cudaGetSymbolAddress((void**)&pAh, g_Ah);
    cudaGetSymbolAddress((void**)&pAl, g_Al);
    cudaGetSymbolAddress((void**)&pAp, g_Ap);
    cudaGetSymbolAddress((void**)&pw1h, g_w1h);
    cudaGetSymbolAddress((void**)&pw1l, g_w1l);
    cudaGetSymbolAddress((void**)&pw1p, g_w1p);
    cudaGetSymbolAddress((void**)&pw2h, g_w2h);
    cudaGetSymbolAddress((void**)&pw2l, g_w2l);
    cudaGetSymbolAddress((void**)&pw2p, g_w2p);

    static cudaStream_t s2 = nullptr;
    static cudaEvent_t evFork, evW1, evW2, evBp;
    if (!s2) {
        cudaStreamCreateWithFlags(&s2, cudaStreamNonBlocking);
        cudaEventCreateWithFlags(&evFork, cudaEventDisableTiming);
        cudaEventCreateWithFlags(&evW1, cudaEventDisableTiming);
        cudaEventCreateWithFlags(&evW2, cudaEventDisableTiming);
        cudaEventCreateWithFlags(&evBp, cudaEventDisableTiming);
        cudaFuncSetAttribute(k_gemm1_hmma, cudaFuncAttributeMaxDynamicSharedMemorySize, 2 * STAGEB);
        cudaFuncSetAttribute(k_gemm2_hmma, cudaFuncAttributeMaxDynamicSharedMemorySize, 2 * STAGEB);
        cudaFuncSetAttribute(k_gemm1_fp16, cudaFuncAttributeMaxDynamicSharedMemorySize, 2 * STAGE2B);
        cudaFuncSetAttribute(k_gemm2_fp16, cudaFuncAttributeMaxDynamicSharedMemorySize, 2 * STAGE2B);
        cudaFuncSetAttribute(k_proj_fp16, cudaFuncAttributeMaxDynamicSharedMemorySize, 2 * STAGE2B);
    }

    // ---- fork: weight prep ----
    cudaEventRecord(evFork, 0);
    cudaStreamWaitEvent(s2, evFork, 0);
    k_tspl3<<<dim3(Fn / 32, Dn / 64, En), 256, 0, s2>>>(w1, pw1h, pw1l, pw1p, Dn, Fn);
    cudaEventRecord(evW1, s2);
    k_tspl3<<<dim3(Dn / 32, Fn / 64, En), 256, 0, s2>>>(w2, pw2h, pw2l, pw2p, Fn, Dn);
    cudaEventRecord(evW2, s2);
    k_cvt16<<<(Vn * Dn / 4 + 255) / 256, 256, 0, s2>>>(embed, pBp, Vn * Dn / 4);
    cudaEventRecord(evBp, s2);

    // ---- main chain ----
    k_embed<<<(Tn * Dn / 4) / 256, 256>>>(ids, embed);

    float* hin = hA;
    float* hout = hB;
    for (int hop = 0; hop < 2; hop++) {
        k_router2<<<Tn / 8, 256>>>(hin, router + (size_t)hop * Dn * En);
        k_scan<<<1, 256>>>();
        k_prep_h<<<Tn, 256>>>(hin, hout, pAh, pAl, pAp, hop);
        if (hop == 0) {
            cudaStreamWaitEvent(0, evW1, 0);
            k_gemm1_hmma<<<dim3(Fn / 128, (CAPn + 127) / 128, En), 256, 2 * STAGEB>>>(pAh, pAl);
            cudaStreamWaitEvent(0, evW2, 0);
            k_gemm2_hmma<<<dim3(Dn / 128, (CAPn + 127) / 128, En), 256, 2 * STAGEB>>>(hout);
        } else {
            cudaStreamWaitEvent(0, evW1, 0);
            k_gemm1_fp16<<<dim3(Fn / 128, (CAPn + 127) / 128, En), 256, 2 * STAGE2B>>>(pAp);
            cudaStreamWaitEvent(0, evW2, 0);
            k_gemm2_fp16<<<dim3(Dn / 128, (CAPn + 127) / 128, En), 256, 2 * STAGE2B>>>(hout);
        }
        float* tmp = hin; hin = hout; hout = tmp;
    }
    k_rms_fp16<<<Tn, 256>>>(hin, lnw, pAp);

    cudaStreamWaitEvent(0, evBp, 0);
    k_proj_fp16<<<dim3(Tn / 128, Vn / 128), 256, 2 * STAGE2B>>>(pAp, pBp, out);
}